// round 15
// baseline (speedup 1.0000x reference)
#include <cuda_runtime.h>
#include <cuda_bf16.h>
#include <cuda_fp16.h>
#include <cstdint>
#include <math.h>

#define Bn 4
#define Sn 2048
#define Dn 1024
#define Hn 16
#define DHn 64
#define Mn (Bn * Sn)   // 8192

#define PGRID 296      // persistent grid: <= 2 CTAs/SM on 148+ SM parts

// ---------------------------------------------------------------------------
// Device scratch
// ---------------------------------------------------------------------------
__device__ float g_AO[Mn * Dn];

__device__ __nv_bfloat16 g_hA_hi[Mn * Dn];
__device__ __nv_bfloat16 g_hA_lo[Mn * Dn];
__device__ __half        g_hF_hi[Mn * Dn];
__device__ __half        g_hF_lo[Mn * Dn];
__device__ __nv_bfloat16 g_W_hi[2 * Dn * Dn];   // bf16 [N,K]: q, k
__device__ __nv_bfloat16 g_W_lo[2 * Dn * Dn];
__device__ __half        g_Wf[2 * Dn * Dn];     // fp16 [N,K]: v, o

__device__ __nv_bfloat16 g_Qh[Mn * Dn];  // pre-scaled by 0.125*log2(e)
__device__ __nv_bfloat16 g_Ql[Mn * Dn];
__device__ __nv_bfloat16 g_Kh[Mn * Dn];
__device__ __nv_bfloat16 g_Kl[Mn * Dn];
__device__ __half        g_Vf[Mn * Dn];
__device__ __half        g_AVfh[Mn * Dn];
__device__ __half        g_AVfl[Mn * Dn];

// ---------------------------------------------------------------------------
__device__ __forceinline__ uint32_t smem_u32(const void* p) {
    uint32_t a;
    asm("{ .reg .u64 t; cvta.to.shared.u64 t, %1; cvt.u32.u64 %0, t; }"
        : "=r"(a) : "l"(p));
    return a;
}

__device__ __forceinline__ float fast_ex2(float x) {
    float r;
    asm("ex2.approx.ftz.f32 %0, %1;" : "=f"(r) : "f"(x));
    return r;
}

__device__ __forceinline__ uint32_t pack_f16x2(float lo, float hi) {
    uint32_t d;
    asm("cvt.rn.f16x2.f32 %0, %1, %2;" : "=r"(d) : "f"(hi), "f"(lo));
    return d;
}

__device__ __forceinline__ void ldm_x4(uint32_t* r, uint32_t addr) {
    asm volatile("ldmatrix.sync.aligned.m8n8.x4.shared.b16 {%0,%1,%2,%3}, [%4];"
                 : "=r"(r[0]), "=r"(r[1]), "=r"(r[2]), "=r"(r[3]) : "r"(addr));
}
__device__ __forceinline__ void ldm_x4t(uint32_t* r, uint32_t addr) {
    asm volatile("ldmatrix.sync.aligned.m8n8.x4.trans.shared.b16 {%0,%1,%2,%3}, [%4];"
                 : "=r"(r[0]), "=r"(r[1]), "=r"(r[2]), "=r"(r[3]) : "r"(addr));
}

__device__ __forceinline__ void mma_bf16(float* c, const uint32_t* a,
                                         uint32_t b0, uint32_t b1) {
    asm volatile(
        "mma.sync.aligned.m16n8k16.row.col.f32.bf16.bf16.f32 "
        "{%0,%1,%2,%3}, {%4,%5,%6,%7}, {%8,%9}, {%0,%1,%2,%3};"
        : "+f"(c[0]), "+f"(c[1]), "+f"(c[2]), "+f"(c[3])
        : "r"(a[0]), "r"(a[1]), "r"(a[2]), "r"(a[3]), "r"(b0), "r"(b1));
}

__device__ __forceinline__ void mma_fp16(float* c, const uint32_t* a,
                                         uint32_t b0, uint32_t b1) {
    asm volatile(
        "mma.sync.aligned.m16n8k16.row.col.f32.f16.f16.f32 "
        "{%0,%1,%2,%3}, {%4,%5,%6,%7}, {%8,%9}, {%0,%1,%2,%3};"
        : "+f"(c[0]), "+f"(c[1]), "+f"(c[2]), "+f"(c[3])
        : "r"(a[0]), "r"(a[1]), "r"(a[2]), "r"(a[3]), "r"(b0), "r"(b1));
}

__device__ __forceinline__ void cp16(uint32_t s, const void* g) {
    asm volatile("cp.async.cg.shared.global [%0], [%1], 16;" :: "r"(s), "l"(g));
}
#define CP_COMMIT() asm volatile("cp.async.commit_group;" ::: "memory")
#define CP_WAIT0()  asm volatile("cp.async.wait_group 0;" ::: "memory")
#define CP_WAIT1()  asm volatile("cp.async.wait_group 1;" ::: "memory")

// ---------------------------------------------------------------------------
// Split fp32 h -> bf16 (hi,lo) AND fp16 (hi,lo)
// ---------------------------------------------------------------------------
__global__ __launch_bounds__(256) void split_h(
    const float* __restrict__ x,
    __nv_bfloat16* __restrict__ bhi, __nv_bfloat16* __restrict__ blo,
    __half* __restrict__ fhi, __half* __restrict__ flo)
{
    const int i = (blockIdx.x * 256 + threadIdx.x) * 4;
    float4 v = *(const float4*)(x + i);
    float vv[4] = {v.x, v.y, v.z, v.w};
    __nv_bfloat16 bh[4], bl[4];
    __half fh[4], fl[4];
#pragma unroll
    for (int k = 0; k < 4; k++) {
        bh[k] = __float2bfloat16(vv[k]);
        bl[k] = __float2bfloat16(vv[k] - __bfloat162float(bh[k]));
        fh[k] = __float2half_rn(vv[k]);
        fl[k] = __float2half_rn(vv[k] - __half2float(fh[k]));
    }
    __nv_bfloat162* bhp = (__nv_bfloat162*)(bhi + i);
    __nv_bfloat162* blp = (__nv_bfloat162*)(blo + i);
    bhp[0] = __nv_bfloat162(bh[0], bh[1]); bhp[1] = __nv_bfloat162(bh[2], bh[3]);
    blp[0] = __nv_bfloat162(bl[0], bl[1]); blp[1] = __nv_bfloat162(bl[2], bl[3]);
    __half2* fhp = (__half2*)(fhi + i);
    __half2* flp = (__half2*)(flo + i);
    fhp[0] = __halves2half2(fh[0], fh[1]); fhp[1] = __halves2half2(fh[2], fh[3]);
    flp[0] = __halves2half2(fl[0], fl[1]); flp[1] = __halves2half2(fl[2], fl[3]);
}

// ---------------------------------------------------------------------------
// Split + transpose weights: z=0,1 (Wq,Wk) -> bf16 hi/lo [N,K];
//                            z=2,3 (Wv,Wo) -> fp16 single [N,K].
// ---------------------------------------------------------------------------
__global__ __launch_bounds__(256) void split_T4(
    const float* __restrict__ W0, const float* __restrict__ W1,
    const float* __restrict__ W2, const float* __restrict__ W3,
    __nv_bfloat16* __restrict__ hiT, __nv_bfloat16* __restrict__ loT,
    __half* __restrict__ fT)
{
    const int z = blockIdx.z;
    const float* W = (z == 0) ? W0 : (z == 1) ? W1 : (z == 2) ? W2 : W3;

    __shared__ float t[32][33];
    const int tx = threadIdx.x, ty = threadIdx.y;
    const int bn = blockIdx.x * 32, bk = blockIdx.y * 32;
#pragma unroll
    for (int j = 0; j < 4; j++)
        t[ty + j * 8][tx] = W[(size_t)(bk + ty + j * 8) * Dn + bn + tx];
    __syncthreads();
#pragma unroll
    for (int j = 0; j < 4; j++) {
        float v = t[tx][ty + j * 8];
        size_t o = (size_t)(bn + ty + j * 8) * Dn + bk + tx;
        if (z < 2) {
            __nv_bfloat16 h = __float2bfloat16(v);
            __nv_bfloat16 l = __float2bfloat16(v - __bfloat162float(h));
            hiT[(size_t)z * Dn * Dn + o] = h;
            loT[(size_t)z * Dn * Dn + o] = l;
        } else {
            fT[(size_t)(z - 2) * Dn * Dn + o] = __float2half_rn(v);
        }
    }
}

// ---------------------------------------------------------------------------
// Shared GEMM constants.
// ---------------------------------------------------------------------------
#define BK        32
#define NSTAGE    (Dn / BK)          // 32

#define B_ROW     64
#define B_ARR     (128 * B_ROW)      // 8192
#define B_STAGE   (4 * B_ARR)        // 32768

#define ROW_B     80
#define ARR_SZ    (128 * ROW_B)      // 10240
#define FBUF_SZ   (3 * ARR_SZ)       // 30720

#define GEMM_SMEM (3 * B_STAGE)      // 98304

__device__ __forceinline__ uint32_t bswz(int row, int chunk) {
    return (uint32_t)(row * B_ROW) + (uint32_t)((chunk ^ ((row >> 1) & 3)) << 4);
}

// ---------------------------------------------------------------------------
// bf16 3-term GEMM body (Q/K projections), 3-stage cp.async ring.
// ---------------------------------------------------------------------------
__device__ __forceinline__ void gemm_bf16_body(
    const __nv_bfloat16* __restrict__ Ahi, const __nv_bfloat16* __restrict__ Alo,
    const __nv_bfloat16* __restrict__ Bhi, const __nv_bfloat16* __restrict__ Blo,
    __nv_bfloat16* __restrict__ Chi, __nv_bfloat16* __restrict__ Clo, float scale,
    int m0, int n0)
{
    extern __shared__ char smem[];
    const uint32_t sb = smem_u32(smem);
    const int tid  = threadIdx.x;
    const int wid  = tid >> 5;
    const int lane = tid & 31;
    const int m0w = (wid & 1) * 64;
    const int n0w = (wid >> 1) * 32;

    const int lr = tid >> 2;
    const int lc = tid & 3;
    const uint32_t s0 = bswz(lr, lc);
    const uint32_t s1 = s0 + 64 * B_ROW;
    const size_t gA0 = (size_t)(m0 + lr) * 2048 + lc * 16;
    const size_t gA1 = gA0 + (size_t)64 * 2048;
    const size_t gB0 = (size_t)(n0 + lr) * 2048 + lc * 16;
    const size_t gB1 = gB0 + (size_t)64 * 2048;
    const char* pAhi = (const char*)Ahi;
    const char* pAlo = (const char*)Alo;
    const char* pBhi = (const char*)Bhi;
    const char* pBlo = (const char*)Blo;

    float acc[4][4][4];
#pragma unroll
    for (int i = 0; i < 4; i++)
#pragma unroll
        for (int j = 0; j < 4; j++)
#pragma unroll
            for (int k = 0; k < 4; k++) acc[i][j][k] = 0.f;

    const int lrow = lane & 15;
    const int lch  = lane >> 4;
    uint32_t a_rb[4], b_rb[2];
    int a_x[4], b_x[2];
#pragma unroll
    for (int mi = 0; mi < 4; mi++) {
        int r = m0w + mi * 16 + lrow;
        a_rb[mi] = (uint32_t)r * B_ROW;
        a_x[mi]  = (r >> 1) & 3;
    }
#pragma unroll
    for (int ni = 0; ni < 2; ni++) {
        int r = n0w + ni * 16 + lrow;
        b_rb[ni] = (uint32_t)r * B_ROW;
        b_x[ni]  = (r >> 1) & 3;
    }

#define B_LD_STAGE(st_, kc_) do {                                             \
    const size_t kb_ = (size_t)(kc_) * 64;                                    \
    const uint32_t db_ = sb + (uint32_t)(st_) * B_STAGE;                      \
    cp16(db_ + 0 * B_ARR + s0, pAhi + gA0 + kb_);                             \
    cp16(db_ + 0 * B_ARR + s1, pAhi + gA1 + kb_);                             \
    cp16(db_ + 1 * B_ARR + s0, pAlo + gA0 + kb_);                             \
    cp16(db_ + 1 * B_ARR + s1, pAlo + gA1 + kb_);                             \
    cp16(db_ + 2 * B_ARR + s0, pBhi + gB0 + kb_);                             \
    cp16(db_ + 2 * B_ARR + s1, pBhi + gB1 + kb_);                             \
    cp16(db_ + 3 * B_ARR + s0, pBlo + gB0 + kb_);                             \
    cp16(db_ + 3 * B_ARR + s1, pBlo + gB1 + kb_);                             \
    CP_COMMIT();                                                              \
} while (0)

    B_LD_STAGE(0, 0);
    B_LD_STAGE(1, 1);
    __syncthreads();

    for (int kc = 0; kc < NSTAGE; kc++) {
        if (kc + 1 < NSTAGE) { CP_WAIT1(); } else { CP_WAIT0(); }
        __syncthreads();

        if (kc + 2 < NSTAGE)
            B_LD_STAGE((kc + 2) % 3, kc + 2);

        const uint32_t bufb = sb + (uint32_t)(kc % 3) * B_STAGE;
#pragma unroll
        for (int ks = 0; ks < 2; ks++) {
            uint32_t ah[4][4], bh[2][4];
#pragma unroll
            for (int mi = 0; mi < 4; mi++)
                ldm_x4(ah[mi], bufb + 0 * B_ARR + a_rb[mi]
                                 + (uint32_t)(((ks * 2 + lch) ^ a_x[mi]) << 4));
#pragma unroll
            for (int ni = 0; ni < 2; ni++)
                ldm_x4(bh[ni], bufb + 2 * B_ARR + b_rb[ni]
                                 + (uint32_t)(((ks * 2 + lch) ^ b_x[ni]) << 4));
#pragma unroll
            for (int mi = 0; mi < 4; mi++)
#pragma unroll
                for (int ni = 0; ni < 2; ni++) {
                    mma_bf16(acc[mi][ni * 2 + 0], ah[mi], bh[ni][0], bh[ni][2]);
                    mma_bf16(acc[mi][ni * 2 + 1], ah[mi], bh[ni][1], bh[ni][3]);
                }
            {
                uint32_t bl[2][4];
#pragma unroll
                for (int ni = 0; ni < 2; ni++)
                    ldm_x4(bl[ni], bufb + 3 * B_ARR + b_rb[ni]
                                     + (uint32_t)(((ks * 2 + lch) ^ b_x[ni]) << 4));
#pragma unroll
                for (int mi = 0; mi < 4; mi++)
#pragma unroll
                    for (int ni = 0; ni < 2; ni++) {
                        mma_bf16(acc[mi][ni * 2 + 0], ah[mi], bl[ni][0], bl[ni][2]);
                        mma_bf16(acc[mi][ni * 2 + 1], ah[mi], bl[ni][1], bl[ni][3]);
                    }
            }
            {
                uint32_t al[4][4];
#pragma unroll
                for (int mi = 0; mi < 4; mi++)
                    ldm_x4(al[mi], bufb + 1 * B_ARR + a_rb[mi]
                                     + (uint32_t)(((ks * 2 + lch) ^ a_x[mi]) << 4));
#pragma unroll
                for (int mi = 0; mi < 4; mi++)
#pragma unroll
                    for (int ni = 0; ni < 2; ni++) {
                        mma_bf16(acc[mi][ni * 2 + 0], al[mi], bh[ni][0], bh[ni][2]);
                        mma_bf16(acc[mi][ni * 2 + 1], al[mi], bh[ni][1], bh[ni][3]);
                    }
            }
        }
    }
#undef B_LD_STAGE

    const int erow = lane >> 2;
    const int ecol = (lane & 3) * 2;
#pragma unroll
    for (int mi = 0; mi < 4; mi++) {
#pragma unroll
        for (int nj = 0; nj < 4; nj++) {
            size_t base0 = (size_t)(m0 + m0w + mi * 16 + erow) * Dn
                         + n0 + n0w + nj * 8 + ecol;
#pragma unroll
            for (int half = 0; half < 2; half++) {
                size_t b = base0 + half * 8 * Dn;
                float v0 = acc[mi][nj][half * 2 + 0] * scale;
                float v1 = acc[mi][nj][half * 2 + 1] * scale;
                __nv_bfloat16 h0 = __float2bfloat16(v0);
                __nv_bfloat16 h1 = __float2bfloat16(v1);
                __nv_bfloat16 l0 = __float2bfloat16(v0 - __bfloat162float(h0));
                __nv_bfloat16 l1 = __float2bfloat16(v1 - __bfloat162float(h1));
                *(__nv_bfloat162*)(Chi + b) = __nv_bfloat162(h0, h1);
                *(__nv_bfloat162*)(Clo + b) = __nv_bfloat162(l0, l1);
            }
        }
    }
}

// ---------------------------------------------------------------------------
// fp16 2-term GEMM body (V and O projections), 3-stage cp.async ring.
// ---------------------------------------------------------------------------
template <int EPI>
__device__ __forceinline__ void gemm_fp16_body(
    const __half* __restrict__ Ahi, const __half* __restrict__ Alo,
    const __half* __restrict__ Bf,
    float* __restrict__ C, __half* __restrict__ Cf,
    int m0, int n0)
{
    extern __shared__ char smem[];
    const uint32_t sb = smem_u32(smem);
    const int tid  = threadIdx.x;
    const int wid  = tid >> 5;
    const int lane = tid & 31;
    const int m0w = (wid & 1) * 64;
    const int n0w = (wid >> 1) * 32;

    const int lr = tid >> 2;
    const int lc = tid & 3;
    const uint32_t soff0 = lr * ROW_B + lc * 16;
    const uint32_t soff1 = (lr + 64) * ROW_B + lc * 16;
    const size_t gA0 = (size_t)(m0 + lr) * 2048 + lc * 16;
    const size_t gA1 = gA0 + (size_t)64 * 2048;
    const size_t gB0 = (size_t)(n0 + lr) * 2048 + lc * 16;
    const size_t gB1 = gB0 + (size_t)64 * 2048;
    const char* pAhi = (const char*)Ahi;
    const char* pAlo = (const char*)Alo;
    const char* pBf  = (const char*)Bf;

    float acc[4][4][4];
#pragma unroll
    for (int i = 0; i < 4; i++)
#pragma unroll
        for (int j = 0; j < 4; j++)
#pragma unroll
            for (int k = 0; k < 4; k++) acc[i][j][k] = 0.f;

    const int lrow = lane & 15;
    const int lch  = lane >> 4;
    const uint32_t a_lbase = (uint32_t)(m0w + lrow) * ROW_B + lch * 16;
    const uint32_t b_lbase = (uint32_t)(n0w + lrow) * ROW_B + lch * 16;

#define F_LD_STAGE(st_, kc_) do {                                             \
    const size_t kb_ = (size_t)(kc_) * 64;                                    \
    const uint32_t db_ = sb + (uint32_t)(st_) * FBUF_SZ;                      \
    cp16(db_ + 0 * ARR_SZ + soff0, pAhi + gA0 + kb_);                         \
    cp16(db_ + 0 * ARR_SZ + soff1, pAhi + gA1 + kb_);                         \
    cp16(db_ + 1 * ARR_SZ + soff0, pAlo + gA0 + kb_);                         \
    cp16(db_ + 1 * ARR_SZ + soff1, pAlo + gA1 + kb_);                         \
    cp16(db_ + 2 * ARR_SZ + soff0, pBf + gB0 + kb_);                          \
    cp16(db_ + 2 * ARR_SZ + soff1, pBf + gB1 + kb_);                          \
    CP_COMMIT();                                                              \
} while (0)

    F_LD_STAGE(0, 0);
    F_LD_STAGE(1, 1);
    __syncthreads();

    for (int kc = 0; kc < NSTAGE; kc++) {
        if (kc + 1 < NSTAGE) { CP_WAIT1(); } else { CP_WAIT0(); }
        __syncthreads();

        if (kc + 2 < NSTAGE)
            F_LD_STAGE((kc + 2) % 3, kc + 2);

        const uint32_t bufb = sb + (uint32_t)(kc % 3) * FBUF_SZ;
#pragma unroll
        for (int ks = 0; ks < 2; ks++) {
            uint32_t ah[4][4], bf_[2][4];
#pragma unroll
            for (int mi = 0; mi < 4; mi++)
                ldm_x4(ah[mi], bufb + 0 * ARR_SZ + a_lbase
                                 + mi * (16 * ROW_B) + ks * 32);
#pragma unroll
            for (int ni = 0; ni < 2; ni++)
                ldm_x4(bf_[ni], bufb + 2 * ARR_SZ + b_lbase
                                  + ni * (16 * ROW_B) + ks * 32);
#pragma unroll
            for (int mi = 0; mi < 4; mi++)
#pragma unroll
                for (int ni = 0; ni < 2; ni++) {
                    mma_fp16(acc[mi][ni * 2 + 0], ah[mi], bf_[ni][0], bf_[ni][2]);
                    mma_fp16(acc[mi][ni * 2 + 1], ah[mi], bf_[ni][1], bf_[ni][3]);
                }
            {
                uint32_t al[4][4];
#pragma unroll
                for (int mi = 0; mi < 4; mi++)
                    ldm_x4(al[mi], bufb + 1 * ARR_SZ + a_lbase
                                     + mi * (16 * ROW_B) + ks * 32);
#pragma unroll
                for (int mi = 0; mi < 4; mi++)
#pragma unroll
                    for (int ni = 0; ni < 2; ni++) {
                        mma_fp16(acc[mi][ni * 2 + 0], al[mi], bf_[ni][0], bf_[ni][2]);
                        mma_fp16(acc[mi][ni * 2 + 1], al[mi], bf_[ni][1], bf_[ni][3]);
                    }
            }
        }
    }
#undef F_LD_STAGE

    const int erow = lane >> 2;
    const int ecol = (lane & 3) * 2;
#pragma unroll
    for (int mi = 0; mi < 4; mi++) {
#pragma unroll
        for (int nj = 0; nj < 4; nj++) {
            size_t base0 = (size_t)(m0 + m0w + mi * 16 + erow) * Dn
                         + n0 + n0w + nj * 8 + ecol;
            if (EPI == 0) {
                *(float2*)(C + base0)          = make_float2(acc[mi][nj][0], acc[mi][nj][1]);
                *(float2*)(C + base0 + 8 * Dn) = make_float2(acc[mi][nj][2], acc[mi][nj][3]);
            } else {
#pragma unroll
                for (int half = 0; half < 2; half++) {
                    size_t b = base0 + half * 8 * Dn;
                    uint32_t p = pack_f16x2(acc[mi][nj][half * 2 + 0],
                                            acc[mi][nj][half * 2 + 1]);
                    *(uint32_t*)(Cf + b) = p;
                }
            }
        }
    }
}

// Persistent fused Q/K/V projection: 1536 units over PGRID CTAs.
__global__ __launch_bounds__(256, 2) void gemm_qkv(
    const __nv_bfloat16* __restrict__ Ahi, const __nv_bfloat16* __restrict__ Alo,
    const __half* __restrict__ Fhi, const __half* __restrict__ Flo,
    const __nv_bfloat16* __restrict__ Whi, const __nv_bfloat16* __restrict__ Wlo,
    const __half* __restrict__ Wf,
    __nv_bfloat16* __restrict__ Qh, __nv_bfloat16* __restrict__ Ql,
    __nv_bfloat16* __restrict__ Kh, __nv_bfloat16* __restrict__ Kl,
    __half* __restrict__ Vf, float qscale)
{
    for (int unit = blockIdx.x; unit < 24 * 64; unit += PGRID) {
        __syncthreads();    // protect smem ring reuse across units
        const int ng   = (unit % 24) * 128;
        const int wsel = ng >> 10;
        const int n0   = ng & 1023;
        const int m0   = (unit / 24) * 128;
        if (wsel == 0)
            gemm_bf16_body(Ahi, Alo, Whi, Wlo, Qh, Ql, qscale, m0, n0);
        else if (wsel == 1)
            gemm_bf16_body(Ahi, Alo, Whi + (size_t)Dn * Dn, Wlo + (size_t)Dn * Dn,
                           Kh, Kl, 1.0f, m0, n0);
        else
            gemm_fp16_body<2>(Fhi, Flo, Wf, nullptr, Vf, m0, n0);
    }
}

// Persistent O projection: 512 units.
__global__ __launch_bounds__(256, 2) void gemm_o(
    const __half* __restrict__ AVhi, const __half* __restrict__ AVlo,
    const __half* __restrict__ Wof, float* __restrict__ C)
{
    for (int unit = blockIdx.x; unit < 8 * 64; unit += PGRID) {
        __syncthreads();
        gemm_fp16_body<0>(AVhi, AVlo, Wof, C, nullptr,
                          (unit / 8) * 128, (unit % 8) * 128);
    }
}

// ---------------------------------------------------------------------------
// Persistent flash attention: 1024 units ((qt,hh,bb)) over PGRID CTAs.
// QK^T = 3-term bf16 split; P*V = single fp16 MMA. Q frags in registers.
// ---------------------------------------------------------------------------
#define FROW 144
#define FARR (64 * FROW)          // 9216
#define QARR (128 * FROW)         // 18432
#define KVBUF (3 * FARR)          // 27648
#define FLASH_SMEM (QARR + 3 * KVBUF)   // 101376 -> 2 CTAs/SM

#define KV_PREFETCH(kt_, buf_) do {                                           \
    const uint32_t base_ = sb + QARR + (uint32_t)(buf_) * KVBUF;              \
    const size_t g0_ = (size_t)(bb * Sn + (kt_) * 64 + kr0) * Dn              \
                     + headoff + kch * 8;                                     \
    const size_t g1_ = g0_ + (size_t)32 * Dn;                                 \
    cp16(base_ + 0 * FARR + kso0, g_Kh + g0_);                                \
    cp16(base_ + 0 * FARR + kso1, g_Kh + g1_);                                \
    cp16(base_ + 1 * FARR + kso0, g_Kl + g0_);                                \
    cp16(base_ + 1 * FARR + kso1, g_Kl + g1_);                                \
    cp16(base_ + 2 * FARR + kso0, g_Vf + g0_);                                \
    cp16(base_ + 2 * FARR + kso1, g_Vf + g1_);                                \
    CP_COMMIT();                                                              \
} while (0)

__global__ __launch_bounds__(256, 2) void flash_mma()
{
    extern __shared__ char sm[];
    const uint32_t sb = smem_u32(sm);
    const int tid = threadIdx.x;
    const int lane = tid & 31;
    const int w = tid >> 5;

    const int kr0 = tid >> 3;
    const int kch = tid & 7;
    const uint32_t kso0 = (uint32_t)kr0 * FROW + kch * 16;
    const uint32_t kso1 = (uint32_t)(kr0 + 32) * FROW + kch * 16;

    const int lrow = lane & 15;
    const int lch  = lane >> 4;
    const uint32_t aoff = (uint32_t)(w * 16 + lrow) * FROW + lch * 16;
    uint32_t boff[4];
#pragma unroll
    for (int np = 0; np < 4; np++)
        boff[np] = (uint32_t)(np * 16 + lrow) * FROW + lch * 16;
    const uint32_t qlbase = QARR + 2 * KVBUF;

    for (int unit = blockIdx.x; unit < 16 * Hn * Bn; unit += PGRID) {
        const int qt = unit & 15;
        const int hh = (unit >> 4) & 15;
        const int bb = unit >> 8;
        const size_t headoff = (size_t)hh * 64;

        __syncthreads();   // previous unit's smem reads fully done

        // Prologue: stage Qh in [0,QARR), Ql in ring buffer 2 area.
#pragma unroll
        for (int i = 0; i < 4; i++) {
            const int idx = tid + 256 * i;
            const int r = idx >> 3, ch = idx & 7;
            const size_t g = (size_t)(bb * Sn + qt * 128 + r) * Dn
                           + headoff + ch * 8;
            const uint32_t so = r * FROW + ch * 16;
            *(uint4*)(sm + so)          = *(const uint4*)(g_Qh + g);
            *(uint4*)(sm + qlbase + so) = *(const uint4*)(g_Ql + g);
        }
        KV_PREFETCH(0, 0);
        KV_PREFETCH(1, 1);
        __syncthreads();

        uint32_t qhf[4][4], qlf[4][4];
#pragma unroll
        for (int ks = 0; ks < 4; ks++) {
            ldm_x4(qhf[ks], sb + aoff + ks * 32);
            ldm_x4(qlf[ks], sb + qlbase + aoff + ks * 32);
        }

        float o[8][4];
#pragma unroll
        for (int j = 0; j < 8; j++)
#pragma unroll
            for (int k = 0; k < 4; k++) o[j][k] = 0.f;
        float m0r = -1e30f, m1r = -1e30f, l0r = 0.f, l1r = 0.f;

        for (int kt = 0; kt < Sn / 64; kt++) {
            if (kt + 1 < Sn / 64) { CP_WAIT1(); } else { CP_WAIT0(); }
            __syncthreads();

            if (kt + 2 < Sn / 64)
                KV_PREFETCH(kt + 2, (kt + 2) % 3);

            const uint32_t kvb = sb + QARR + (uint32_t)(kt % 3) * KVBUF;

            float s[8][4];
#pragma unroll
            for (int j = 0; j < 8; j++)
#pragma unroll
                for (int k = 0; k < 4; k++) s[j][k] = 0.f;

#pragma unroll
            for (int ks = 0; ks < 4; ks++) {
#pragma unroll
                for (int np = 0; np < 4; np++) {
                    uint32_t kh[4], kl[4];
                    ldm_x4(kh, kvb + 0 * FARR + boff[np] + ks * 32);
                    ldm_x4(kl, kvb + 1 * FARR + boff[np] + ks * 32);
                    mma_bf16(s[2 * np + 0], qhf[ks], kh[0], kh[2]);
                    mma_bf16(s[2 * np + 1], qhf[ks], kh[1], kh[3]);
                    mma_bf16(s[2 * np + 0], qhf[ks], kl[0], kl[2]);
                    mma_bf16(s[2 * np + 1], qhf[ks], kl[1], kl[3]);
                    mma_bf16(s[2 * np + 0], qlf[ks], kh[0], kh[2]);
                    mma_bf16(s[2 * np + 1], qlf[ks], kh[1], kh[3]);
                }
            }

            float mx0 = -1e30f, mx1 = -1e30f;
#pragma unroll
            for (int j = 0; j < 8; j++) {
                mx0 = fmaxf(mx0, fmaxf(s[j][0], s[j][1]));
                mx1 = fmaxf(mx1, fmaxf(s[j][2], s[j][3]));
            }
            mx0 = fmaxf(mx0, __shfl_xor_sync(0xffffffffu, mx0, 1));
            mx0 = fmaxf(mx0, __shfl_xor_sync(0xffffffffu, mx0, 2));
            mx1 = fmaxf(mx1, __shfl_xor_sync(0xffffffffu, mx1, 1));
            mx1 = fmaxf(mx1, __shfl_xor_sync(0xffffffffu, mx1, 2));

            const float mn0 = fmaxf(m0r, mx0);
            const float mn1 = fmaxf(m1r, mx1);
            float a0 = 1.0f, a1 = 1.0f;
            const bool upd = (mn0 > m0r) || (mn1 > m1r);
            if (__any_sync(0xffffffffu, upd)) {
                a0 = fast_ex2(m0r - mn0);
                a1 = fast_ex2(m1r - mn1);
#pragma unroll
                for (int j = 0; j < 8; j++) {
                    o[j][0] *= a0; o[j][1] *= a0;
                    o[j][2] *= a1; o[j][3] *= a1;
                }
            }
            m0r = mn0; m1r = mn1;

            float sum0 = 0.f, sum1 = 0.f;
#pragma unroll
            for (int ks = 0; ks < 4; ks++) {
                uint32_t ap[4];
#pragma unroll
                for (int jj = 0; jj < 2; jj++) {
                    const int j = 2 * ks + jj;
                    float p00 = fast_ex2(s[j][0] - mn0);
                    float p01 = fast_ex2(s[j][1] - mn0);
                    float p10 = fast_ex2(s[j][2] - mn1);
                    float p11 = fast_ex2(s[j][3] - mn1);
                    sum0 += p00 + p01;
                    sum1 += p10 + p11;
                    ap[jj * 2 + 0] = pack_f16x2(p00, p01);
                    ap[jj * 2 + 1] = pack_f16x2(p10, p11);
                }
                const uint32_t vbase = (uint32_t)(ks * 16 + lrow) * FROW + lch * 16;
#pragma unroll
                for (int np = 0; np < 4; np++) {
                    uint32_t vf[4];
                    ldm_x4t(vf, kvb + 2 * FARR + vbase + np * 32);
                    mma_fp16(o[2 * np + 0], ap, vf[0], vf[1]);
                    mma_fp16(o[2 * np + 1], ap, vf[2], vf[3]);
                }
            }
            sum0 += __shfl_xor_sync(0xffffffffu, sum0, 1);
            sum0 += __shfl_xor_sync(0xffffffffu, sum0, 2);
            sum1 += __shfl_xor_sync(0xffffffffu, sum1, 1);
            sum1 += __shfl_xor_sync(0xffffffffu, sum1, 2);
            l0r = l0r * a0 + sum0;
            l1r = l1r * a1 + sum1;
        }

        // Epilogue: normalize, split to fp16 hi/lo, write AV
        const float inv0 = 1.0f / l0r;
        const float inv1 = 1.0f / l1r;
        const size_t row0 = (size_t)(bb * Sn + qt * 128 + w * 16 + (lane >> 2));
        const size_t row1 = row0 + 8;
        const size_t colb = headoff + (lane & 3) * 2;
#pragma unroll
        for (int j = 0; j < 8; j++) {
            float v0 = o[j][0] * inv0, v1 = o[j][1] * inv0;
            float v2 = o[j][2] * inv1, v3 = o[j][3] * inv1;
            __half h0 = __float2half_rn(v0);
            __half h1 = __float2half_rn(v1);
            __half h2 = __float2half_rn(v2);
            __half h3 = __float2half_rn(v3);
            size_t b0 = row0 * Dn + colb + j * 8;
            size_t b1 = row1 * Dn + colb + j * 8;
            *(__half2*)(g_AVfh + b0) = __halves2half2(h0, h1);
            *(__half2*)(g_AVfh + b1) = __halves2half2(h2, h3);
            *(__half2*)(g_AVfl + b0) =
                __halves2half2(__float2half_rn(v0 - __half2float(h0)),
                               __float2half_rn(v1 - __half2float(h1)));
            *(__half2*)(g_AVfl + b1) =
                __halves2half2(__float2half_rn(v2 - __half2float(h2)),
                               __float2half_rn(v3 - __half2float(h3)));
        }
    }
}

// ---------------------------------------------------------------------------
// Residual + LayerNorm
// ---------------------------------------------------------------------------
__global__ __launch_bounds__(256) void ln_residual(
    const float* __restrict__ h, const float* __restrict__ gamma,
    const float* __restrict__ beta, float* __restrict__ out)
{
    const int row = blockIdx.x;
    const int tid = threadIdx.x;

    const float4 hv = *(const float4*)(h + row * Dn + tid * 4);
    const float4 av = *(const float4*)(g_AO + row * Dn + tid * 4);
    float4 x = make_float4(hv.x + av.x, hv.y + av.y, hv.z + av.z, hv.w + av.w);

    float s  = x.x + x.y + x.z + x.w;
    float ss = x.x * x.x + x.y * x.y + x.z * x.z + x.w * x.w;
#pragma unroll
    for (int off = 16; off > 0; off >>= 1) {
        s  += __shfl_xor_sync(0xffffffffu, s, off);
        ss += __shfl_xor_sync(0xffffffffu, ss, off);
    }
    __shared__ float rs[8], rss[8];
    if ((tid & 31) == 0) { rs[tid >> 5] = s; rss[tid >> 5] = ss; }
    __syncthreads();
    s = 0.f; ss = 0.f;
#pragma unroll
    for (int w = 0; w < 8; w++) { s += rs[w]; ss += rss[w]; }

    const float mu  = s * (1.0f / Dn);
    const float var = ss * (1.0f / Dn) - mu * mu;
    const float inv = rsqrtf(var + 1e-5f);

    const float4 g4 = *(const float4*)(gamma + tid * 4);
    const float4 b4 = *(const float4*)(beta + tid * 4);
    float4 r;
    r.x = g4.x * (x.x - mu) * inv + b4.x;
    r.y = g4.y * (x.y - mu) * inv + b4.y;
    r.z = g4.z * (x.z - mu) * inv + b4.z;
    r.w = g4.w * (x.w - mu) * inv + b4.w;
    *(float4*)(out + row * Dn + tid * 4) = r;
}

// ---------------------------------------------------------------------------
extern "C" void kernel_launch(void* const* d_in, const int* in_sizes, int n_in,
                              void* d_out, int out_size)
{
    (void)in_sizes; (void)n_in; (void)out_size;
    const float* h     = (const float*)d_in[0];
    const float* Wq    = (const float*)d_in[1];
    const float* Wk    = (const float*)d_in[2];
    const float* Wv    = (const float*)d_in[3];
    const float* Wo    = (const float*)d_in[4];
    const float* gamma = (const float*)d_in[5];
    const float* beta  = (const float*)d_in[6];
    float* out = (float*)d_out;

    float* AOp;
    __nv_bfloat16 *hAhi, *hAlo, *Whi, *Wlo, *Qh, *Ql, *Kh, *Kl;
    __half *hFhi, *hFlo, *Wf, *Vf, *AVfh, *AVfl;
    cudaGetSymbolAddress((void**)&AOp,  g_AO);
    cudaGetSymbolAddress((void**)&hAhi, g_hA_hi);
    cudaGetSymbolAddress((void**)&hAlo, g_hA_lo);
    cudaGetSymbolAddress((void**)&hFhi, g_hF_hi);
    cudaGetSymbolAddress((void**)&hFlo, g_hF_lo);
    cudaGetSymbolAddress((void**)&Whi,  g_W_hi);
    cudaGetSymbolAddress((void**)&Wlo,  g_W_lo);
    cudaGetSymbolAddress((void**)&Wf,   g_Wf);
    cudaGetSymbolAddress((void**)&Qh,   g_Qh);
    cudaGetSymbolAddress((void**)&Ql,   g_Ql);
    cudaGetSymbolAddress((void**)&Kh,   g_Kh);
    cudaGetSymbolAddress((void**)&Kl,   g_Kl);
    cudaGetSymbolAddress((void**)&Vf,   g_Vf);
    cudaGetSymbolAddress((void**)&AVfh, g_AVfh);
    cudaGetSymbolAddress((void**)&AVfl, g_AVfl);

    cudaFuncSetAttribute(gemm_qkv, cudaFuncAttributeMaxDynamicSharedMemorySize,
                         GEMM_SMEM);
    cudaFuncSetAttribute(gemm_o, cudaFuncAttributeMaxDynamicSharedMemorySize,
                         GEMM_SMEM);
    cudaFuncSetAttribute(flash_mma, cudaFuncAttributeMaxDynamicSharedMemorySize,
                         FLASH_SMEM);

    // Split h (bf16 + fp16 pairs) and weights
    split_h<<<Mn * Dn / 1024, 256>>>(h, hAhi, hAlo, hFhi, hFlo);
    split_T4<<<dim3(32, 32, 4), dim3(32, 8)>>>(Wq, Wk, Wv, Wo, Whi, Wlo, Wf);

    // Fused Q/K/V projections (persistent)
    const float QSCALE = 0.125f * 1.4426950408889634f;
    gemm_qkv<<<PGRID, 256, GEMM_SMEM>>>(
        hAhi, hAlo, hFhi, hFlo, Whi, Wlo, Wf, Qh, Ql, Kh, Kl, Vf, QSCALE);

    // Attention (persistent tensorized flash)
    flash_mma<<<PGRID, 256, FLASH_SMEM>>>();

    // Output projection (persistent)
    gemm_o<<<PGRID, 256, GEMM_SMEM>>>(AVfh, AVfl, Wf + (size_t)Dn * Dn, AOp);

    ln_residual<<<Mn, 256>>>(h, gamma, beta, out);
}

// round 16
// speedup vs baseline: 1.1898x; 1.1898x over previous
#include <cuda_runtime.h>
#include <cuda_bf16.h>
#include <cuda_fp16.h>
#include <cstdint>
#include <math.h>

#define Bn 4
#define Sn 2048
#define Dn 1024
#define Hn 16
#define DHn 64
#define Mn (Bn * Sn)   // 8192

// ---------------------------------------------------------------------------
// Device scratch
// ---------------------------------------------------------------------------
__device__ float g_AO[Mn * Dn];

__device__ __nv_bfloat16 g_hA_hi[Mn * Dn];
__device__ __nv_bfloat16 g_hA_lo[Mn * Dn];
__device__ __half        g_hF[Mn * Dn];        // fp16 single h (for V gemm)
__device__ __nv_bfloat16 g_W_hi[2 * Dn * Dn];  // bf16 [N,K]: q, k
__device__ __nv_bfloat16 g_W_lo[2 * Dn * Dn];
__device__ __half        g_Wf[2 * Dn * Dn];    // fp16 [N,K]: v, o

__device__ __nv_bfloat16 g_Qh[Mn * Dn];  // pre-scaled by 0.125*log2(e)
__device__ __nv_bfloat16 g_Ql[Mn * Dn];
__device__ __nv_bfloat16 g_Kh[Mn * Dn];
__device__ __nv_bfloat16 g_Kl[Mn * Dn];
__device__ __half        g_Vf[Mn * Dn];  // V in single fp16
__device__ __half        g_AVf[Mn * Dn]; // AV in single fp16

// ---------------------------------------------------------------------------
__device__ __forceinline__ uint32_t smem_u32(const void* p) {
    uint32_t a;
    asm("{ .reg .u64 t; cvta.to.shared.u64 t, %1; cvt.u32.u64 %0, t; }"
        : "=r"(a) : "l"(p));
    return a;
}

__device__ __forceinline__ float fast_ex2(float x) {
    float r;
    asm("ex2.approx.ftz.f32 %0, %1;" : "=f"(r) : "f"(x));
    return r;
}

__device__ __forceinline__ uint32_t pack_f16x2(float lo, float hi) {
    uint32_t d;
    asm("cvt.rn.f16x2.f32 %0, %1, %2;" : "=r"(d) : "f"(hi), "f"(lo));
    return d;
}

__device__ __forceinline__ void ldm_x4(uint32_t* r, uint32_t addr) {
    asm volatile("ldmatrix.sync.aligned.m8n8.x4.shared.b16 {%0,%1,%2,%3}, [%4];"
                 : "=r"(r[0]), "=r"(r[1]), "=r"(r[2]), "=r"(r[3]) : "r"(addr));
}
__device__ __forceinline__ void ldm_x4t(uint32_t* r, uint32_t addr) {
    asm volatile("ldmatrix.sync.aligned.m8n8.x4.trans.shared.b16 {%0,%1,%2,%3}, [%4];"
                 : "=r"(r[0]), "=r"(r[1]), "=r"(r[2]), "=r"(r[3]) : "r"(addr));
}

__device__ __forceinline__ void mma_bf16(float* c, const uint32_t* a,
                                         uint32_t b0, uint32_t b1) {
    asm volatile(
        "mma.sync.aligned.m16n8k16.row.col.f32.bf16.bf16.f32 "
        "{%0,%1,%2,%3}, {%4,%5,%6,%7}, {%8,%9}, {%0,%1,%2,%3};"
        : "+f"(c[0]), "+f"(c[1]), "+f"(c[2]), "+f"(c[3])
        : "r"(a[0]), "r"(a[1]), "r"(a[2]), "r"(a[3]), "r"(b0), "r"(b1));
}

__device__ __forceinline__ void mma_fp16(float* c, const uint32_t* a,
                                         uint32_t b0, uint32_t b1) {
    asm volatile(
        "mma.sync.aligned.m16n8k16.row.col.f32.f16.f16.f32 "
        "{%0,%1,%2,%3}, {%4,%5,%6,%7}, {%8,%9}, {%0,%1,%2,%3};"
        : "+f"(c[0]), "+f"(c[1]), "+f"(c[2]), "+f"(c[3])
        : "r"(a[0]), "r"(a[1]), "r"(a[2]), "r"(a[3]), "r"(b0), "r"(b1));
}

__device__ __forceinline__ void cp16(uint32_t s, const void* g) {
    asm volatile("cp.async.cg.shared.global [%0], [%1], 16;" :: "r"(s), "l"(g));
}
#define CP_COMMIT() asm volatile("cp.async.commit_group;" ::: "memory")
#define CP_WAIT0()  asm volatile("cp.async.wait_group 0;" ::: "memory")
#define CP_WAIT1()  asm volatile("cp.async.wait_group 1;" ::: "memory")

// ---------------------------------------------------------------------------
// Split fp32 h -> bf16 (hi,lo) AND fp16 single
// ---------------------------------------------------------------------------
__global__ __launch_bounds__(256) void split_h(
    const float* __restrict__ x,
    __nv_bfloat16* __restrict__ bhi, __nv_bfloat16* __restrict__ blo,
    __half* __restrict__ f)
{
    const int i = (blockIdx.x * 256 + threadIdx.x) * 4;
    float4 v = *(const float4*)(x + i);
    float vv[4] = {v.x, v.y, v.z, v.w};
    __nv_bfloat16 bh[4], bl[4];
    __half fh[4];
#pragma unroll
    for (int k = 0; k < 4; k++) {
        bh[k] = __float2bfloat16(vv[k]);
        bl[k] = __float2bfloat16(vv[k] - __bfloat162float(bh[k]));
        fh[k] = __float2half_rn(vv[k]);
    }
    __nv_bfloat162* bhp = (__nv_bfloat162*)(bhi + i);
    __nv_bfloat162* blp = (__nv_bfloat162*)(blo + i);
    bhp[0] = __nv_bfloat162(bh[0], bh[1]); bhp[1] = __nv_bfloat162(bh[2], bh[3]);
    blp[0] = __nv_bfloat162(bl[0], bl[1]); blp[1] = __nv_bfloat162(bl[2], bl[3]);
    __half2* fp = (__half2*)(f + i);
    fp[0] = __halves2half2(fh[0], fh[1]); fp[1] = __halves2half2(fh[2], fh[3]);
}

// ---------------------------------------------------------------------------
// Split + transpose weights: z=0,1 (Wq,Wk) -> bf16 hi/lo [N,K];
//                            z=2,3 (Wv,Wo) -> fp16 single [N,K].
// ---------------------------------------------------------------------------
__global__ __launch_bounds__(256) void split_T4(
    const float* __restrict__ W0, const float* __restrict__ W1,
    const float* __restrict__ W2, const float* __restrict__ W3,
    __nv_bfloat16* __restrict__ hiT, __nv_bfloat16* __restrict__ loT,
    __half* __restrict__ fT)
{
    const int z = blockIdx.z;
    const float* W = (z == 0) ? W0 : (z == 1) ? W1 : (z == 2) ? W2 : W3;

    __shared__ float t[32][33];
    const int tx = threadIdx.x, ty = threadIdx.y;
    const int bn = blockIdx.x * 32, bk = blockIdx.y * 32;
#pragma unroll
    for (int j = 0; j < 4; j++)
        t[ty + j * 8][tx] = W[(size_t)(bk + ty + j * 8) * Dn + bn + tx];
    __syncthreads();
#pragma unroll
    for (int j = 0; j < 4; j++) {
        float v = t[tx][ty + j * 8];
        size_t o = (size_t)(bn + ty + j * 8) * Dn + bk + tx;
        if (z < 2) {
            __nv_bfloat16 h = __float2bfloat16(v);
            __nv_bfloat16 l = __float2bfloat16(v - __bfloat162float(h));
            hiT[(size_t)z * Dn * Dn + o] = h;
            loT[(size_t)z * Dn * Dn + o] = l;
        } else {
            fT[(size_t)(z - 2) * Dn * Dn + o] = __float2half_rn(v);
        }
    }
}

// ---------------------------------------------------------------------------
// Shared GEMM constants.
// ---------------------------------------------------------------------------
#define BK        32
#define NSTAGE    (Dn / BK)          // 32

#define B_ROW     64
#define B_ARR     (128 * B_ROW)      // 8192
#define B_STAGE   (4 * B_ARR)        // 32768

#define ROW_B     80
#define ARR_SZ    (128 * ROW_B)      // 10240
#define FBUF_SZ   (2 * ARR_SZ)       // 20480 (A, B only - single term)

#define GEMM_SMEM (3 * B_STAGE)      // 98304 (covers fp16's 3*FBUF=61440)

__device__ __forceinline__ uint32_t bswz(int row, int chunk) {
    return (uint32_t)(row * B_ROW) + (uint32_t)((chunk ^ ((row >> 1) & 3)) << 4);
}

// ---------------------------------------------------------------------------
// bf16 3-term GEMM body (Q/K projections), 3-stage cp.async ring.
// ---------------------------------------------------------------------------
__device__ __forceinline__ void gemm_bf16_body(
    const __nv_bfloat16* __restrict__ Ahi, const __nv_bfloat16* __restrict__ Alo,
    const __nv_bfloat16* __restrict__ Bhi, const __nv_bfloat16* __restrict__ Blo,
    __nv_bfloat16* __restrict__ Chi, __nv_bfloat16* __restrict__ Clo, float scale,
    int m0, int n0)
{
    extern __shared__ char smem[];
    const uint32_t sb = smem_u32(smem);
    const int tid  = threadIdx.x;
    const int wid  = tid >> 5;
    const int lane = tid & 31;
    const int m0w = (wid & 1) * 64;
    const int n0w = (wid >> 1) * 32;

    const int lr = tid >> 2;
    const int lc = tid & 3;
    const uint32_t s0 = bswz(lr, lc);
    const uint32_t s1 = s0 + 64 * B_ROW;
    const size_t gA0 = (size_t)(m0 + lr) * 2048 + lc * 16;
    const size_t gA1 = gA0 + (size_t)64 * 2048;
    const size_t gB0 = (size_t)(n0 + lr) * 2048 + lc * 16;
    const size_t gB1 = gB0 + (size_t)64 * 2048;
    const char* pAhi = (const char*)Ahi;
    const char* pAlo = (const char*)Alo;
    const char* pBhi = (const char*)Bhi;
    const char* pBlo = (const char*)Blo;

    float acc[4][4][4];
#pragma unroll
    for (int i = 0; i < 4; i++)
#pragma unroll
        for (int j = 0; j < 4; j++)
#pragma unroll
            for (int k = 0; k < 4; k++) acc[i][j][k] = 0.f;

    const int lrow = lane & 15;
    const int lch  = lane >> 4;
    uint32_t a_rb[4], b_rb[2];
    int a_x[4], b_x[2];
#pragma unroll
    for (int mi = 0; mi < 4; mi++) {
        int r = m0w + mi * 16 + lrow;
        a_rb[mi] = (uint32_t)r * B_ROW;
        a_x[mi]  = (r >> 1) & 3;
    }
#pragma unroll
    for (int ni = 0; ni < 2; ni++) {
        int r = n0w + ni * 16 + lrow;
        b_rb[ni] = (uint32_t)r * B_ROW;
        b_x[ni]  = (r >> 1) & 3;
    }

#define B_LD_STAGE(st_, kc_) do {                                             \
    const size_t kb_ = (size_t)(kc_) * 64;                                    \
    const uint32_t db_ = sb + (uint32_t)(st_) * B_STAGE;                      \
    cp16(db_ + 0 * B_ARR + s0, pAhi + gA0 + kb_);                             \
    cp16(db_ + 0 * B_ARR + s1, pAhi + gA1 + kb_);                             \
    cp16(db_ + 1 * B_ARR + s0, pAlo + gA0 + kb_);                             \
    cp16(db_ + 1 * B_ARR + s1, pAlo + gA1 + kb_);                             \
    cp16(db_ + 2 * B_ARR + s0, pBhi + gB0 + kb_);                             \
    cp16(db_ + 2 * B_ARR + s1, pBhi + gB1 + kb_);                             \
    cp16(db_ + 3 * B_ARR + s0, pBlo + gB0 + kb_);                             \
    cp16(db_ + 3 * B_ARR + s1, pBlo + gB1 + kb_);                             \
    CP_COMMIT();                                                              \
} while (0)

    B_LD_STAGE(0, 0);
    B_LD_STAGE(1, 1);
    __syncthreads();

    for (int kc = 0; kc < NSTAGE; kc++) {
        if (kc + 1 < NSTAGE) { CP_WAIT1(); } else { CP_WAIT0(); }
        __syncthreads();

        if (kc + 2 < NSTAGE)
            B_LD_STAGE((kc + 2) % 3, kc + 2);

        const uint32_t bufb = sb + (uint32_t)(kc % 3) * B_STAGE;
#pragma unroll
        for (int ks = 0; ks < 2; ks++) {
            uint32_t ah[4][4], bh[2][4];
#pragma unroll
            for (int mi = 0; mi < 4; mi++)
                ldm_x4(ah[mi], bufb + 0 * B_ARR + a_rb[mi]
                                 + (uint32_t)(((ks * 2 + lch) ^ a_x[mi]) << 4));
#pragma unroll
            for (int ni = 0; ni < 2; ni++)
                ldm_x4(bh[ni], bufb + 2 * B_ARR + b_rb[ni]
                                 + (uint32_t)(((ks * 2 + lch) ^ b_x[ni]) << 4));
#pragma unroll
            for (int mi = 0; mi < 4; mi++)
#pragma unroll
                for (int ni = 0; ni < 2; ni++) {
                    mma_bf16(acc[mi][ni * 2 + 0], ah[mi], bh[ni][0], bh[ni][2]);
                    mma_bf16(acc[mi][ni * 2 + 1], ah[mi], bh[ni][1], bh[ni][3]);
                }
            {
                uint32_t bl[2][4];
#pragma unroll
                for (int ni = 0; ni < 2; ni++)
                    ldm_x4(bl[ni], bufb + 3 * B_ARR + b_rb[ni]
                                     + (uint32_t)(((ks * 2 + lch) ^ b_x[ni]) << 4));
#pragma unroll
                for (int mi = 0; mi < 4; mi++)
#pragma unroll
                    for (int ni = 0; ni < 2; ni++) {
                        mma_bf16(acc[mi][ni * 2 + 0], ah[mi], bl[ni][0], bl[ni][2]);
                        mma_bf16(acc[mi][ni * 2 + 1], ah[mi], bl[ni][1], bl[ni][3]);
                    }
            }
            {
                uint32_t al[4][4];
#pragma unroll
                for (int mi = 0; mi < 4; mi++)
                    ldm_x4(al[mi], bufb + 1 * B_ARR + a_rb[mi]
                                     + (uint32_t)(((ks * 2 + lch) ^ a_x[mi]) << 4));
#pragma unroll
                for (int mi = 0; mi < 4; mi++)
#pragma unroll
                    for (int ni = 0; ni < 2; ni++) {
                        mma_bf16(acc[mi][ni * 2 + 0], al[mi], bh[ni][0], bh[ni][2]);
                        mma_bf16(acc[mi][ni * 2 + 1], al[mi], bh[ni][1], bh[ni][3]);
                    }
            }
        }
    }
#undef B_LD_STAGE

    const int erow = lane >> 2;
    const int ecol = (lane & 3) * 2;
#pragma unroll
    for (int mi = 0; mi < 4; mi++) {
#pragma unroll
        for (int nj = 0; nj < 4; nj++) {
            size_t base0 = (size_t)(m0 + m0w + mi * 16 + erow) * Dn
                         + n0 + n0w + nj * 8 + ecol;
#pragma unroll
            for (int half = 0; half < 2; half++) {
                size_t b = base0 + half * 8 * Dn;
                float v0 = acc[mi][nj][half * 2 + 0] * scale;
                float v1 = acc[mi][nj][half * 2 + 1] * scale;
                __nv_bfloat16 h0 = __float2bfloat16(v0);
                __nv_bfloat16 h1 = __float2bfloat16(v1);
                __nv_bfloat16 l0 = __float2bfloat16(v0 - __bfloat162float(h0));
                __nv_bfloat16 l1 = __float2bfloat16(v1 - __bfloat162float(h1));
                *(__nv_bfloat162*)(Chi + b) = __nv_bfloat162(h0, h1);
                *(__nv_bfloat162*)(Clo + b) = __nv_bfloat162(l0, l1);
            }
        }
    }
}

// ---------------------------------------------------------------------------
// fp16 SINGLE-term GEMM body (V and O projections), 3-stage cp.async ring.
// EPI = 0: fp32 output C.  EPI = 2: fp16 single output Cf.
// ---------------------------------------------------------------------------
template <int EPI>
__device__ __forceinline__ void gemm_fp16_body(
    const __half* __restrict__ Af, const __half* __restrict__ Bf,
    float* __restrict__ C, __half* __restrict__ Cf,
    int m0, int n0)
{
    extern __shared__ char smem[];
    const uint32_t sb = smem_u32(smem);
    const int tid  = threadIdx.x;
    const int wid  = tid >> 5;
    const int lane = tid & 31;
    const int m0w = (wid & 1) * 64;
    const int n0w = (wid >> 1) * 32;

    const int lr = tid >> 2;
    const int lc = tid & 3;
    const uint32_t soff0 = lr * ROW_B + lc * 16;
    const uint32_t soff1 = (lr + 64) * ROW_B + lc * 16;
    const size_t gA0 = (size_t)(m0 + lr) * 2048 + lc * 16;
    const size_t gA1 = gA0 + (size_t)64 * 2048;
    const size_t gB0 = (size_t)(n0 + lr) * 2048 + lc * 16;
    const size_t gB1 = gB0 + (size_t)64 * 2048;
    const char* pAf = (const char*)Af;
    const char* pBf = (const char*)Bf;

    float acc[4][4][4];
#pragma unroll
    for (int i = 0; i < 4; i++)
#pragma unroll
        for (int j = 0; j < 4; j++)
#pragma unroll
            for (int k = 0; k < 4; k++) acc[i][j][k] = 0.f;

    const int lrow = lane & 15;
    const int lch  = lane >> 4;
    const uint32_t a_lbase = (uint32_t)(m0w + lrow) * ROW_B + lch * 16;
    const uint32_t b_lbase = (uint32_t)(n0w + lrow) * ROW_B + lch * 16;

#define F_LD_STAGE(st_, kc_) do {                                             \
    const size_t kb_ = (size_t)(kc_) * 64;                                    \
    const uint32_t db_ = sb + (uint32_t)(st_) * FBUF_SZ;                      \
    cp16(db_ + 0 * ARR_SZ + soff0, pAf + gA0 + kb_);                          \
    cp16(db_ + 0 * ARR_SZ + soff1, pAf + gA1 + kb_);                          \
    cp16(db_ + 1 * ARR_SZ + soff0, pBf + gB0 + kb_);                          \
    cp16(db_ + 1 * ARR_SZ + soff1, pBf + gB1 + kb_);                          \
    CP_COMMIT();                                                              \
} while (0)

    F_LD_STAGE(0, 0);
    F_LD_STAGE(1, 1);
    __syncthreads();

    for (int kc = 0; kc < NSTAGE; kc++) {
        if (kc + 1 < NSTAGE) { CP_WAIT1(); } else { CP_WAIT0(); }
        __syncthreads();

        if (kc + 2 < NSTAGE)
            F_LD_STAGE((kc + 2) % 3, kc + 2);

        const uint32_t bufb = sb + (uint32_t)(kc % 3) * FBUF_SZ;
#pragma unroll
        for (int ks = 0; ks < 2; ks++) {
            uint32_t ah[4][4], bf_[2][4];
#pragma unroll
            for (int mi = 0; mi < 4; mi++)
                ldm_x4(ah[mi], bufb + 0 * ARR_SZ + a_lbase
                                 + mi * (16 * ROW_B) + ks * 32);
#pragma unroll
            for (int ni = 0; ni < 2; ni++)
                ldm_x4(bf_[ni], bufb + 1 * ARR_SZ + b_lbase
                                  + ni * (16 * ROW_B) + ks * 32);
#pragma unroll
            for (int mi = 0; mi < 4; mi++)
#pragma unroll
                for (int ni = 0; ni < 2; ni++) {
                    mma_fp16(acc[mi][ni * 2 + 0], ah[mi], bf_[ni][0], bf_[ni][2]);
                    mma_fp16(acc[mi][ni * 2 + 1], ah[mi], bf_[ni][1], bf_[ni][3]);
                }
        }
    }
#undef F_LD_STAGE

    const int erow = lane >> 2;
    const int ecol = (lane & 3) * 2;
#pragma unroll
    for (int mi = 0; mi < 4; mi++) {
#pragma unroll
        for (int nj = 0; nj < 4; nj++) {
            size_t base0 = (size_t)(m0 + m0w + mi * 16 + erow) * Dn
                         + n0 + n0w + nj * 8 + ecol;
            if (EPI == 0) {
                *(float2*)(C + base0)          = make_float2(acc[mi][nj][0], acc[mi][nj][1]);
                *(float2*)(C + base0 + 8 * Dn) = make_float2(acc[mi][nj][2], acc[mi][nj][3]);
            } else {
#pragma unroll
                for (int half = 0; half < 2; half++) {
                    size_t b = base0 + half * 8 * Dn;
                    uint32_t p = pack_f16x2(acc[mi][nj][half * 2 + 0],
                                            acc[mi][nj][half * 2 + 1]);
                    *(uint32_t*)(Cf + b) = p;
                }
            }
        }
    }
}

// Fused Q/K/V projection: grid (24, 64); blockIdx.x selects weight + outputs.
__global__ __launch_bounds__(256, 2) void gemm_qkv(
    const __nv_bfloat16* __restrict__ Ahi, const __nv_bfloat16* __restrict__ Alo,
    const __half* __restrict__ Af,
    const __nv_bfloat16* __restrict__ Whi, const __nv_bfloat16* __restrict__ Wlo,
    const __half* __restrict__ Wf,
    __nv_bfloat16* __restrict__ Qh, __nv_bfloat16* __restrict__ Ql,
    __nv_bfloat16* __restrict__ Kh, __nv_bfloat16* __restrict__ Kl,
    __half* __restrict__ Vf, float qscale)
{
    const int ng   = blockIdx.x * 128;
    const int wsel = ng >> 10;
    const int n0   = ng & 1023;
    const int m0   = blockIdx.y * 128;
    if (wsel == 0)
        gemm_bf16_body(Ahi, Alo, Whi, Wlo, Qh, Ql, qscale, m0, n0);
    else if (wsel == 1)
        gemm_bf16_body(Ahi, Alo, Whi + (size_t)Dn * Dn, Wlo + (size_t)Dn * Dn,
                       Kh, Kl, 1.0f, m0, n0);
    else
        gemm_fp16_body<2>(Af, Wf, nullptr, Vf, m0, n0);
}

// O projection: fp16 single-term, fp32 output
__global__ __launch_bounds__(256, 2) void gemm_o(
    const __half* __restrict__ AVf, const __half* __restrict__ Wof,
    float* __restrict__ C)
{
    gemm_fp16_body<0>(AVf, Wof, C, nullptr,
                      blockIdx.y * 128, blockIdx.x * 128);
}

// ---------------------------------------------------------------------------
// Flash attention: QK^T = 3-term bf16 split; P*V = single fp16 MMA.
// Q frags in registers, 3-stage KV ring, JIT exp/pack, rescale skip.
// Epilogue writes AV as single fp16.
// ---------------------------------------------------------------------------
#define FROW 144
#define FARR (64 * FROW)          // 9216
#define QARR (128 * FROW)         // 18432
#define KVBUF (3 * FARR)          // 27648
#define FLASH_SMEM (QARR + 3 * KVBUF)   // 101376 -> 2 CTAs/SM

#define KV_PREFETCH(kt_, buf_) do {                                           \
    const uint32_t base_ = sb + QARR + (uint32_t)(buf_) * KVBUF;              \
    const size_t g0_ = (size_t)(bb * Sn + (kt_) * 64 + kr0) * Dn              \
                     + headoff + kch * 8;                                     \
    const size_t g1_ = g0_ + (size_t)32 * Dn;                                 \
    cp16(base_ + 0 * FARR + kso0, g_Kh + g0_);                                \
    cp16(base_ + 0 * FARR + kso1, g_Kh + g1_);                                \
    cp16(base_ + 1 * FARR + kso0, g_Kl + g0_);                                \
    cp16(base_ + 1 * FARR + kso1, g_Kl + g1_);                                \
    cp16(base_ + 2 * FARR + kso0, g_Vf + g0_);                                \
    cp16(base_ + 2 * FARR + kso1, g_Vf + g1_);                                \
    CP_COMMIT();                                                              \
} while (0)

__global__ __launch_bounds__(256, 2) void flash_mma()
{
    extern __shared__ char sm[];
    const uint32_t sb = smem_u32(sm);
    const int tid = threadIdx.x;
    const int lane = tid & 31;
    const int w = tid >> 5;
    const int qt = blockIdx.x, hh = blockIdx.y, bb = blockIdx.z;

    const size_t headoff = (size_t)hh * 64;

    const int kr0 = tid >> 3;
    const int kch = tid & 7;
    const uint32_t kso0 = (uint32_t)kr0 * FROW + kch * 16;
    const uint32_t kso1 = (uint32_t)(kr0 + 32) * FROW + kch * 16;

    // Prologue: stage Qh in [0,QARR), Ql in ring buffer 2 area.
    const uint32_t qlbase = QARR + 2 * KVBUF;
#pragma unroll
    for (int i = 0; i < 4; i++) {
        const int idx = tid + 256 * i;
        const int r = idx >> 3, ch = idx & 7;
        const size_t g = (size_t)(bb * Sn + qt * 128 + r) * Dn + headoff + ch * 8;
        const uint32_t so = r * FROW + ch * 16;
        *(uint4*)(sm + so)          = *(const uint4*)(g_Qh + g);
        *(uint4*)(sm + qlbase + so) = *(const uint4*)(g_Ql + g);
    }
    KV_PREFETCH(0, 0);
    KV_PREFETCH(1, 1);
    __syncthreads();

    const int lrow = lane & 15;
    const int lch  = lane >> 4;
    const uint32_t aoff = (uint32_t)(w * 16 + lrow) * FROW + lch * 16;
    uint32_t boff[4];
#pragma unroll
    for (int np = 0; np < 4; np++)
        boff[np] = (uint32_t)(np * 16 + lrow) * FROW + lch * 16;

    uint32_t qhf[4][4], qlf[4][4];
#pragma unroll
    for (int ks = 0; ks < 4; ks++) {
        ldm_x4(qhf[ks], sb + aoff + ks * 32);
        ldm_x4(qlf[ks], sb + qlbase + aoff + ks * 32);
    }

    float o[8][4];
#pragma unroll
    for (int j = 0; j < 8; j++)
#pragma unroll
        for (int k = 0; k < 4; k++) o[j][k] = 0.f;
    float m0r = -1e30f, m1r = -1e30f, l0r = 0.f, l1r = 0.f;

    for (int kt = 0; kt < Sn / 64; kt++) {
        if (kt + 1 < Sn / 64) { CP_WAIT1(); } else { CP_WAIT0(); }
        __syncthreads();

        if (kt + 2 < Sn / 64)
            KV_PREFETCH(kt + 2, (kt + 2) % 3);

        const uint32_t kvb = sb + QARR + (uint32_t)(kt % 3) * KVBUF;

        float s[8][4];
#pragma unroll
        for (int j = 0; j < 8; j++)
#pragma unroll
            for (int k = 0; k < 4; k++) s[j][k] = 0.f;

#pragma unroll
        for (int ks = 0; ks < 4; ks++) {
#pragma unroll
            for (int np = 0; np < 4; np++) {
                uint32_t kh[4], kl[4];
                ldm_x4(kh, kvb + 0 * FARR + boff[np] + ks * 32);
                ldm_x4(kl, kvb + 1 * FARR + boff[np] + ks * 32);
                mma_bf16(s[2 * np + 0], qhf[ks], kh[0], kh[2]);
                mma_bf16(s[2 * np + 1], qhf[ks], kh[1], kh[3]);
                mma_bf16(s[2 * np + 0], qhf[ks], kl[0], kl[2]);
                mma_bf16(s[2 * np + 1], qhf[ks], kl[1], kl[3]);
                mma_bf16(s[2 * np + 0], qlf[ks], kh[0], kh[2]);
                mma_bf16(s[2 * np + 1], qlf[ks], kh[1], kh[3]);
            }
        }

        float mx0 = -1e30f, mx1 = -1e30f;
#pragma unroll
        for (int j = 0; j < 8; j++) {
            mx0 = fmaxf(mx0, fmaxf(s[j][0], s[j][1]));
            mx1 = fmaxf(mx1, fmaxf(s[j][2], s[j][3]));
        }
        mx0 = fmaxf(mx0, __shfl_xor_sync(0xffffffffu, mx0, 1));
        mx0 = fmaxf(mx0, __shfl_xor_sync(0xffffffffu, mx0, 2));
        mx1 = fmaxf(mx1, __shfl_xor_sync(0xffffffffu, mx1, 1));
        mx1 = fmaxf(mx1, __shfl_xor_sync(0xffffffffu, mx1, 2));

        const float mn0 = fmaxf(m0r, mx0);
        const float mn1 = fmaxf(m1r, mx1);
        float a0 = 1.0f, a1 = 1.0f;
        const bool upd = (mn0 > m0r) || (mn1 > m1r);
        if (__any_sync(0xffffffffu, upd)) {
            a0 = fast_ex2(m0r - mn0);
            a1 = fast_ex2(m1r - mn1);
#pragma unroll
            for (int j = 0; j < 8; j++) {
                o[j][0] *= a0; o[j][1] *= a0;
                o[j][2] *= a1; o[j][3] *= a1;
            }
        }
        m0r = mn0; m1r = mn1;

        float sum0 = 0.f, sum1 = 0.f;
#pragma unroll
        for (int ks = 0; ks < 4; ks++) {
            uint32_t ap[4];
#pragma unroll
            for (int jj = 0; jj < 2; jj++) {
                const int j = 2 * ks + jj;
                float p00 = fast_ex2(s[j][0] - mn0);
                float p01 = fast_ex2(s[j][1] - mn0);
                float p10 = fast_ex2(s[j][2] - mn1);
                float p11 = fast_ex2(s[j][3] - mn1);
                sum0 += p00 + p01;
                sum1 += p10 + p11;
                ap[jj * 2 + 0] = pack_f16x2(p00, p01);
                ap[jj * 2 + 1] = pack_f16x2(p10, p11);
            }
            const uint32_t vbase = (uint32_t)(ks * 16 + lrow) * FROW + lch * 16;
#pragma unroll
            for (int np = 0; np < 4; np++) {
                uint32_t vf[4];
                ldm_x4t(vf, kvb + 2 * FARR + vbase + np * 32);
                mma_fp16(o[2 * np + 0], ap, vf[0], vf[1]);
                mma_fp16(o[2 * np + 1], ap, vf[2], vf[3]);
            }
        }
        sum0 += __shfl_xor_sync(0xffffffffu, sum0, 1);
        sum0 += __shfl_xor_sync(0xffffffffu, sum0, 2);
        sum1 += __shfl_xor_sync(0xffffffffu, sum1, 1);
        sum1 += __shfl_xor_sync(0xffffffffu, sum1, 2);
        l0r = l0r * a0 + sum0;
        l1r = l1r * a1 + sum1;
    }

    // Epilogue: normalize, write AV as single fp16
    const float inv0 = 1.0f / l0r;
    const float inv1 = 1.0f / l1r;
    const size_t row0 = (size_t)(bb * Sn + qt * 128 + w * 16 + (lane >> 2));
    const size_t row1 = row0 + 8;
    const size_t colb = headoff + (lane & 3) * 2;
#pragma unroll
    for (int j = 0; j < 8; j++) {
        size_t b0 = row0 * Dn + colb + j * 8;
        size_t b1 = row1 * Dn + colb + j * 8;
        *(uint32_t*)(g_AVf + b0) = pack_f16x2(o[j][0] * inv0, o[j][1] * inv0);
        *(uint32_t*)(g_AVf + b1) = pack_f16x2(o[j][2] * inv1, o[j][3] * inv1);
    }
}

// ---------------------------------------------------------------------------
// Residual + LayerNorm
// ---------------------------------------------------------------------------
__global__ __launch_bounds__(256) void ln_residual(
    const float* __restrict__ h, const float* __restrict__ gamma,
    const float* __restrict__ beta, float* __restrict__ out)
{
    const int row = blockIdx.x;
    const int tid = threadIdx.x;

    const float4 hv = *(const float4*)(h + row * Dn + tid * 4);
    const float4 av = *(const float4*)(g_AO + row * Dn + tid * 4);
    float4 x = make_float4(hv.x + av.x, hv.y + av.y, hv.z + av.z, hv.w + av.w);

    float s  = x.x + x.y + x.z + x.w;
    float ss = x.x * x.x + x.y * x.y + x.z * x.z + x.w * x.w;
#pragma unroll
    for (int off = 16; off > 0; off >>= 1) {
        s  += __shfl_xor_sync(0xffffffffu, s, off);
        ss += __shfl_xor_sync(0xffffffffu, ss, off);
    }
    __shared__ float rs[8], rss[8];
    if ((tid & 31) == 0) { rs[tid >> 5] = s; rss[tid >> 5] = ss; }
    __syncthreads();
    s = 0.f; ss = 0.f;
#pragma unroll
    for (int w = 0; w < 8; w++) { s += rs[w]; ss += rss[w]; }

    const float mu  = s * (1.0f / Dn);
    const float var = ss * (1.0f / Dn) - mu * mu;
    const float inv = rsqrtf(var + 1e-5f);

    const float4 g4 = *(const float4*)(gamma + tid * 4);
    const float4 b4 = *(const float4*)(beta + tid * 4);
    float4 r;
    r.x = g4.x * (x.x - mu) * inv + b4.x;
    r.y = g4.y * (x.y - mu) * inv + b4.y;
    r.z = g4.z * (x.z - mu) * inv + b4.z;
    r.w = g4.w * (x.w - mu) * inv + b4.w;
    *(float4*)(out + row * Dn + tid * 4) = r;
}

// ---------------------------------------------------------------------------
extern "C" void kernel_launch(void* const* d_in, const int* in_sizes, int n_in,
                              void* d_out, int out_size)
{
    (void)in_sizes; (void)n_in; (void)out_size;
    const float* h     = (const float*)d_in[0];
    const float* Wq    = (const float*)d_in[1];
    const float* Wk    = (const float*)d_in[2];
    const float* Wv    = (const float*)d_in[3];
    const float* Wo    = (const float*)d_in[4];
    const float* gamma = (const float*)d_in[5];
    const float* beta  = (const float*)d_in[6];
    float* out = (float*)d_out;

    float* AOp;
    __nv_bfloat16 *hAhi, *hAlo, *Whi, *Wlo, *Qh, *Ql, *Kh, *Kl;
    __half *hF, *Wf, *Vf, *AVf;
    cudaGetSymbolAddress((void**)&AOp,  g_AO);
    cudaGetSymbolAddress((void**)&hAhi, g_hA_hi);
    cudaGetSymbolAddress((void**)&hAlo, g_hA_lo);
    cudaGetSymbolAddress((void**)&hF,   g_hF);
    cudaGetSymbolAddress((void**)&Whi,  g_W_hi);
    cudaGetSymbolAddress((void**)&Wlo,  g_W_lo);
    cudaGetSymbolAddress((void**)&Wf,   g_Wf);
    cudaGetSymbolAddress((void**)&Qh,   g_Qh);
    cudaGetSymbolAddress((void**)&Ql,   g_Ql);
    cudaGetSymbolAddress((void**)&Kh,   g_Kh);
    cudaGetSymbolAddress((void**)&Kl,   g_Kl);
    cudaGetSymbolAddress((void**)&Vf,   g_Vf);
    cudaGetSymbolAddress((void**)&AVf,  g_AVf);

    cudaFuncSetAttribute(gemm_qkv, cudaFuncAttributeMaxDynamicSharedMemorySize,
                         GEMM_SMEM);
    cudaFuncSetAttribute(gemm_o, cudaFuncAttributeMaxDynamicSharedMemorySize,
                         GEMM_SMEM);
    cudaFuncSetAttribute(flash_mma, cudaFuncAttributeMaxDynamicSharedMemorySize,
                         FLASH_SMEM);

    // Split h (bf16 pair + fp16 single) and weights
    split_h<<<Mn * Dn / 1024, 256>>>(h, hAhi, hAlo, hF);
    split_T4<<<dim3(32, 32, 4), dim3(32, 8)>>>(Wq, Wk, Wv, Wo, Whi, Wlo, Wf);

    // Fused Q/K/V projections (Q pre-scaled by 1/8 * log2(e); V single fp16)
    const float QSCALE = 0.125f * 1.4426950408889634f;
    gemm_qkv<<<dim3(24, Mn / 128), 256, GEMM_SMEM>>>(
        hAhi, hAlo, hF, Whi, Wlo, Wf, Qh, Ql, Kh, Kl, Vf, QSCALE);

    // Attention (tensorized flash, fp16 PV, fp16 AV out)
    flash_mma<<<dim3(Sn / 128, Hn, Bn), 256, FLASH_SMEM>>>();

    // Output projection (single-term fp16)
    gemm_o<<<dim3(Dn / 128, Mn / 128), 256, GEMM_SMEM>>>(
        AVf, Wf + (size_t)Dn * Dn, AOp);

    ln_residual<<<Mn, 256>>>(h, gamma, beta, out);
}

// round 17
// speedup vs baseline: 1.2266x; 1.0309x over previous
#include <cuda_runtime.h>
#include <cuda_bf16.h>
#include <cuda_fp16.h>
#include <cstdint>
#include <math.h>

#define Bn 4
#define Sn 2048
#define Dn 1024
#define Hn 16
#define DHn 64
#define Mn (Bn * Sn)   // 8192

// ---------------------------------------------------------------------------
// Device scratch
// ---------------------------------------------------------------------------
__device__ float g_AO[Mn * Dn];

__device__ __nv_bfloat16 g_hA_hi[Mn * Dn];
__device__ __nv_bfloat16 g_hA_lo[Mn * Dn];
__device__ __half        g_hF[Mn * Dn];        // fp16 single h (for V gemm)
__device__ __nv_bfloat16 g_W_hi[2 * Dn * Dn];  // bf16 [N,K]: q, k
__device__ __nv_bfloat16 g_W_lo[2 * Dn * Dn];
__device__ __half        g_Wf[2 * Dn * Dn];    // fp16 [N,K]: v, o

__device__ __nv_bfloat16 g_Qh[Mn * Dn];  // pre-scaled by 0.125*log2(e)
__device__ __nv_bfloat16 g_Ql[Mn * Dn];
__device__ __nv_bfloat16 g_Kh[Mn * Dn];
__device__ __nv_bfloat16 g_Kl[Mn * Dn];
__device__ __half        g_Vf[Mn * Dn];  // V in single fp16
__device__ __half        g_AVf[Mn * Dn]; // AV in single fp16

// ---------------------------------------------------------------------------
__device__ __forceinline__ uint32_t smem_u32(const void* p) {
    uint32_t a;
    asm("{ .reg .u64 t; cvta.to.shared.u64 t, %1; cvt.u32.u64 %0, t; }"
        : "=r"(a) : "l"(p));
    return a;
}

__device__ __forceinline__ float fast_ex2(float x) {
    float r;
    asm("ex2.approx.ftz.f32 %0, %1;" : "=f"(r) : "f"(x));
    return r;
}

__device__ __forceinline__ uint32_t pack_f16x2(float lo, float hi) {
    uint32_t d;
    asm("cvt.rn.f16x2.f32 %0, %1, %2;" : "=r"(d) : "f"(hi), "f"(lo));
    return d;
}

__device__ __forceinline__ void ldm_x4(uint32_t* r, uint32_t addr) {
    asm volatile("ldmatrix.sync.aligned.m8n8.x4.shared.b16 {%0,%1,%2,%3}, [%4];"
                 : "=r"(r[0]), "=r"(r[1]), "=r"(r[2]), "=r"(r[3]) : "r"(addr));
}
__device__ __forceinline__ void ldm_x4t(uint32_t* r, uint32_t addr) {
    asm volatile("ldmatrix.sync.aligned.m8n8.x4.trans.shared.b16 {%0,%1,%2,%3}, [%4];"
                 : "=r"(r[0]), "=r"(r[1]), "=r"(r[2]), "=r"(r[3]) : "r"(addr));
}

__device__ __forceinline__ void mma_bf16(float* c, const uint32_t* a,
                                         uint32_t b0, uint32_t b1) {
    asm volatile(
        "mma.sync.aligned.m16n8k16.row.col.f32.bf16.bf16.f32 "
        "{%0,%1,%2,%3}, {%4,%5,%6,%7}, {%8,%9}, {%0,%1,%2,%3};"
        : "+f"(c[0]), "+f"(c[1]), "+f"(c[2]), "+f"(c[3])
        : "r"(a[0]), "r"(a[1]), "r"(a[2]), "r"(a[3]), "r"(b0), "r"(b1));
}

__device__ __forceinline__ void mma_fp16(float* c, const uint32_t* a,
                                         uint32_t b0, uint32_t b1) {
    asm volatile(
        "mma.sync.aligned.m16n8k16.row.col.f32.f16.f16.f32 "
        "{%0,%1,%2,%3}, {%4,%5,%6,%7}, {%8,%9}, {%0,%1,%2,%3};"
        : "+f"(c[0]), "+f"(c[1]), "+f"(c[2]), "+f"(c[3])
        : "r"(a[0]), "r"(a[1]), "r"(a[2]), "r"(a[3]), "r"(b0), "r"(b1));
}

__device__ __forceinline__ void cp16(uint32_t s, const void* g) {
    asm volatile("cp.async.cg.shared.global [%0], [%1], 16;" :: "r"(s), "l"(g));
}
#define CP_COMMIT() asm volatile("cp.async.commit_group;" ::: "memory")
#define CP_WAIT0()  asm volatile("cp.async.wait_group 0;" ::: "memory")
#define CP_WAIT1()  asm volatile("cp.async.wait_group 1;" ::: "memory")
#define CP_WAIT2()  asm volatile("cp.async.wait_group 2;" ::: "memory")

// ---------------------------------------------------------------------------
// Split fp32 h -> bf16 (hi,lo) AND fp16 single
// ---------------------------------------------------------------------------
__global__ __launch_bounds__(256) void split_h(
    const float* __restrict__ x,
    __nv_bfloat16* __restrict__ bhi, __nv_bfloat16* __restrict__ blo,
    __half* __restrict__ f)
{
    const int i = (blockIdx.x * 256 + threadIdx.x) * 4;
    float4 v = *(const float4*)(x + i);
    float vv[4] = {v.x, v.y, v.z, v.w};
    __nv_bfloat16 bh[4], bl[4];
    __half fh[4];
#pragma unroll
    for (int k = 0; k < 4; k++) {
        bh[k] = __float2bfloat16(vv[k]);
        bl[k] = __float2bfloat16(vv[k] - __bfloat162float(bh[k]));
        fh[k] = __float2half_rn(vv[k]);
    }
    __nv_bfloat162* bhp = (__nv_bfloat162*)(bhi + i);
    __nv_bfloat162* blp = (__nv_bfloat162*)(blo + i);
    bhp[0] = __nv_bfloat162(bh[0], bh[1]); bhp[1] = __nv_bfloat162(bh[2], bh[3]);
    blp[0] = __nv_bfloat162(bl[0], bl[1]); blp[1] = __nv_bfloat162(bl[2], bl[3]);
    __half2* fp = (__half2*)(f + i);
    fp[0] = __halves2half2(fh[0], fh[1]); fp[1] = __halves2half2(fh[2], fh[3]);
}

// ---------------------------------------------------------------------------
// Split + transpose weights: z=0,1 (Wq,Wk) -> bf16 hi/lo [N,K];
//                            z=2,3 (Wv,Wo) -> fp16 single [N,K].
// ---------------------------------------------------------------------------
__global__ __launch_bounds__(256) void split_T4(
    const float* __restrict__ W0, const float* __restrict__ W1,
    const float* __restrict__ W2, const float* __restrict__ W3,
    __nv_bfloat16* __restrict__ hiT, __nv_bfloat16* __restrict__ loT,
    __half* __restrict__ fT)
{
    const int z = blockIdx.z;
    const float* W = (z == 0) ? W0 : (z == 1) ? W1 : (z == 2) ? W2 : W3;

    __shared__ float t[32][33];
    const int tx = threadIdx.x, ty = threadIdx.y;
    const int bn = blockIdx.x * 32, bk = blockIdx.y * 32;
#pragma unroll
    for (int j = 0; j < 4; j++)
        t[ty + j * 8][tx] = W[(size_t)(bk + ty + j * 8) * Dn + bn + tx];
    __syncthreads();
#pragma unroll
    for (int j = 0; j < 4; j++) {
        float v = t[tx][ty + j * 8];
        size_t o = (size_t)(bn + ty + j * 8) * Dn + bk + tx;
        if (z < 2) {
            __nv_bfloat16 h = __float2bfloat16(v);
            __nv_bfloat16 l = __float2bfloat16(v - __bfloat162float(h));
            hiT[(size_t)z * Dn * Dn + o] = h;
            loT[(size_t)z * Dn * Dn + o] = l;
        } else {
            fT[(size_t)(z - 2) * Dn * Dn + o] = __float2half_rn(v);
        }
    }
}

// ---------------------------------------------------------------------------
// Shared GEMM constants.
// ---------------------------------------------------------------------------
#define BK        32
#define NSTAGE    (Dn / BK)          // 32

#define B_ROW     64
#define B_ARR     (128 * B_ROW)      // 8192
#define B_STAGE   (4 * B_ARR)        // 32768

#define ROW_B     80
#define ARR_SZ    (128 * ROW_B)      // 10240
#define FBUF_SZ   (2 * ARR_SZ)       // 20480 (A, B only - single term)

#define GEMM_SMEM (3 * B_STAGE)      // 98304

__device__ __forceinline__ uint32_t bswz(int row, int chunk) {
    return (uint32_t)(row * B_ROW) + (uint32_t)((chunk ^ ((row >> 1) & 3)) << 4);
}

// ---------------------------------------------------------------------------
// bf16 3-term GEMM body (Q/K projections), 3-stage cp.async ring.
// ---------------------------------------------------------------------------
__device__ __forceinline__ void gemm_bf16_body(
    const __nv_bfloat16* __restrict__ Ahi, const __nv_bfloat16* __restrict__ Alo,
    const __nv_bfloat16* __restrict__ Bhi, const __nv_bfloat16* __restrict__ Blo,
    __nv_bfloat16* __restrict__ Chi, __nv_bfloat16* __restrict__ Clo, float scale,
    int m0, int n0)
{
    extern __shared__ char smem[];
    const uint32_t sb = smem_u32(smem);
    const int tid  = threadIdx.x;
    const int wid  = tid >> 5;
    const int lane = tid & 31;
    const int m0w = (wid & 1) * 64;
    const int n0w = (wid >> 1) * 32;

    const int lr = tid >> 2;
    const int lc = tid & 3;
    const uint32_t s0 = bswz(lr, lc);
    const uint32_t s1 = s0 + 64 * B_ROW;
    const size_t gA0 = (size_t)(m0 + lr) * 2048 + lc * 16;
    const size_t gA1 = gA0 + (size_t)64 * 2048;
    const size_t gB0 = (size_t)(n0 + lr) * 2048 + lc * 16;
    const size_t gB1 = gB0 + (size_t)64 * 2048;
    const char* pAhi = (const char*)Ahi;
    const char* pAlo = (const char*)Alo;
    const char* pBhi = (const char*)Bhi;
    const char* pBlo = (const char*)Blo;

    float acc[4][4][4];
#pragma unroll
    for (int i = 0; i < 4; i++)
#pragma unroll
        for (int j = 0; j < 4; j++)
#pragma unroll
            for (int k = 0; k < 4; k++) acc[i][j][k] = 0.f;

    const int lrow = lane & 15;
    const int lch  = lane >> 4;
    uint32_t a_rb[4], b_rb[2];
    int a_x[4], b_x[2];
#pragma unroll
    for (int mi = 0; mi < 4; mi++) {
        int r = m0w + mi * 16 + lrow;
        a_rb[mi] = (uint32_t)r * B_ROW;
        a_x[mi]  = (r >> 1) & 3;
    }
#pragma unroll
    for (int ni = 0; ni < 2; ni++) {
        int r = n0w + ni * 16 + lrow;
        b_rb[ni] = (uint32_t)r * B_ROW;
        b_x[ni]  = (r >> 1) & 3;
    }

#define B_LD_STAGE(st_, kc_) do {                                             \
    const size_t kb_ = (size_t)(kc_) * 64;                                    \
    const uint32_t db_ = sb + (uint32_t)(st_) * B_STAGE;                      \
    cp16(db_ + 0 * B_ARR + s0, pAhi + gA0 + kb_);                             \
    cp16(db_ + 0 * B_ARR + s1, pAhi + gA1 + kb_);                             \
    cp16(db_ + 1 * B_ARR + s0, pAlo + gA0 + kb_);                             \
    cp16(db_ + 1 * B_ARR + s1, pAlo + gA1 + kb_);                             \
    cp16(db_ + 2 * B_ARR + s0, pBhi + gB0 + kb_);                             \
    cp16(db_ + 2 * B_ARR + s1, pBhi + gB1 + kb_);                             \
    cp16(db_ + 3 * B_ARR + s0, pBlo + gB0 + kb_);                             \
    cp16(db_ + 3 * B_ARR + s1, pBlo + gB1 + kb_);                             \
    CP_COMMIT();                                                              \
} while (0)

    B_LD_STAGE(0, 0);
    B_LD_STAGE(1, 1);
    __syncthreads();

    for (int kc = 0; kc < NSTAGE; kc++) {
        if (kc + 1 < NSTAGE) { CP_WAIT1(); } else { CP_WAIT0(); }
        __syncthreads();

        if (kc + 2 < NSTAGE)
            B_LD_STAGE((kc + 2) % 3, kc + 2);

        const uint32_t bufb = sb + (uint32_t)(kc % 3) * B_STAGE;
#pragma unroll
        for (int ks = 0; ks < 2; ks++) {
            uint32_t ah[4][4], bh[2][4];
#pragma unroll
            for (int mi = 0; mi < 4; mi++)
                ldm_x4(ah[mi], bufb + 0 * B_ARR + a_rb[mi]
                                 + (uint32_t)(((ks * 2 + lch) ^ a_x[mi]) << 4));
#pragma unroll
            for (int ni = 0; ni < 2; ni++)
                ldm_x4(bh[ni], bufb + 2 * B_ARR + b_rb[ni]
                                 + (uint32_t)(((ks * 2 + lch) ^ b_x[ni]) << 4));
#pragma unroll
            for (int mi = 0; mi < 4; mi++)
#pragma unroll
                for (int ni = 0; ni < 2; ni++) {
                    mma_bf16(acc[mi][ni * 2 + 0], ah[mi], bh[ni][0], bh[ni][2]);
                    mma_bf16(acc[mi][ni * 2 + 1], ah[mi], bh[ni][1], bh[ni][3]);
                }
            {
                uint32_t bl[2][4];
#pragma unroll
                for (int ni = 0; ni < 2; ni++)
                    ldm_x4(bl[ni], bufb + 3 * B_ARR + b_rb[ni]
                                     + (uint32_t)(((ks * 2 + lch) ^ b_x[ni]) << 4));
#pragma unroll
                for (int mi = 0; mi < 4; mi++)
#pragma unroll
                    for (int ni = 0; ni < 2; ni++) {
                        mma_bf16(acc[mi][ni * 2 + 0], ah[mi], bl[ni][0], bl[ni][2]);
                        mma_bf16(acc[mi][ni * 2 + 1], ah[mi], bl[ni][1], bl[ni][3]);
                    }
            }
            {
                uint32_t al[4][4];
#pragma unroll
                for (int mi = 0; mi < 4; mi++)
                    ldm_x4(al[mi], bufb + 1 * B_ARR + a_rb[mi]
                                     + (uint32_t)(((ks * 2 + lch) ^ a_x[mi]) << 4));
#pragma unroll
                for (int mi = 0; mi < 4; mi++)
#pragma unroll
                    for (int ni = 0; ni < 2; ni++) {
                        mma_bf16(acc[mi][ni * 2 + 0], al[mi], bh[ni][0], bh[ni][2]);
                        mma_bf16(acc[mi][ni * 2 + 1], al[mi], bh[ni][1], bh[ni][3]);
                    }
            }
        }
    }
#undef B_LD_STAGE

    const int erow = lane >> 2;
    const int ecol = (lane & 3) * 2;
#pragma unroll
    for (int mi = 0; mi < 4; mi++) {
#pragma unroll
        for (int nj = 0; nj < 4; nj++) {
            size_t base0 = (size_t)(m0 + m0w + mi * 16 + erow) * Dn
                         + n0 + n0w + nj * 8 + ecol;
#pragma unroll
            for (int half = 0; half < 2; half++) {
                size_t b = base0 + half * 8 * Dn;
                float v0 = acc[mi][nj][half * 2 + 0] * scale;
                float v1 = acc[mi][nj][half * 2 + 1] * scale;
                __nv_bfloat16 h0 = __float2bfloat16(v0);
                __nv_bfloat16 h1 = __float2bfloat16(v1);
                __nv_bfloat16 l0 = __float2bfloat16(v0 - __bfloat162float(h0));
                __nv_bfloat16 l1 = __float2bfloat16(v1 - __bfloat162float(h1));
                *(__nv_bfloat162*)(Chi + b) = __nv_bfloat162(h0, h1);
                *(__nv_bfloat162*)(Clo + b) = __nv_bfloat162(l0, l1);
            }
        }
    }
}

// ---------------------------------------------------------------------------
// fp16 SINGLE-term GEMM body (V and O projections), 3-stage cp.async ring.
// EPI = 0: fp32 output C.  EPI = 2: fp16 single output Cf.
// ---------------------------------------------------------------------------
template <int EPI>
__device__ __forceinline__ void gemm_fp16_body(
    const __half* __restrict__ Af, const __half* __restrict__ Bf,
    float* __restrict__ C, __half* __restrict__ Cf,
    int m0, int n0)
{
    extern __shared__ char smem[];
    const uint32_t sb = smem_u32(smem);
    const int tid  = threadIdx.x;
    const int wid  = tid >> 5;
    const int lane = tid & 31;
    const int m0w = (wid & 1) * 64;
    const int n0w = (wid >> 1) * 32;

    const int lr = tid >> 2;
    const int lc = tid & 3;
    const uint32_t soff0 = lr * ROW_B + lc * 16;
    const uint32_t soff1 = (lr + 64) * ROW_B + lc * 16;
    const size_t gA0 = (size_t)(m0 + lr) * 2048 + lc * 16;
    const size_t gA1 = gA0 + (size_t)64 * 2048;
    const size_t gB0 = (size_t)(n0 + lr) * 2048 + lc * 16;
    const size_t gB1 = gB0 + (size_t)64 * 2048;
    const char* pAf = (const char*)Af;
    const char* pBf = (const char*)Bf;

    float acc[4][4][4];
#pragma unroll
    for (int i = 0; i < 4; i++)
#pragma unroll
        for (int j = 0; j < 4; j++)
#pragma unroll
            for (int k = 0; k < 4; k++) acc[i][j][k] = 0.f;

    const int lrow = lane & 15;
    const int lch  = lane >> 4;
    const uint32_t a_lbase = (uint32_t)(m0w + lrow) * ROW_B + lch * 16;
    const uint32_t b_lbase = (uint32_t)(n0w + lrow) * ROW_B + lch * 16;

#define F_LD_STAGE(st_, kc_) do {                                             \
    const size_t kb_ = (size_t)(kc_) * 64;                                    \
    const uint32_t db_ = sb + (uint32_t)(st_) * FBUF_SZ;                      \
    cp16(db_ + 0 * ARR_SZ + soff0, pAf + gA0 + kb_);                          \
    cp16(db_ + 0 * ARR_SZ + soff1, pAf + gA1 + kb_);                          \
    cp16(db_ + 1 * ARR_SZ + soff0, pBf + gB0 + kb_);                          \
    cp16(db_ + 1 * ARR_SZ + soff1, pBf + gB1 + kb_);                          \
    CP_COMMIT();                                                              \
} while (0)

    F_LD_STAGE(0, 0);
    F_LD_STAGE(1, 1);
    __syncthreads();

    for (int kc = 0; kc < NSTAGE; kc++) {
        if (kc + 1 < NSTAGE) { CP_WAIT1(); } else { CP_WAIT0(); }
        __syncthreads();

        if (kc + 2 < NSTAGE)
            F_LD_STAGE((kc + 2) % 3, kc + 2);

        const uint32_t bufb = sb + (uint32_t)(kc % 3) * FBUF_SZ;
#pragma unroll
        for (int ks = 0; ks < 2; ks++) {
            uint32_t ah[4][4], bf_[2][4];
#pragma unroll
            for (int mi = 0; mi < 4; mi++)
                ldm_x4(ah[mi], bufb + 0 * ARR_SZ + a_lbase
                                 + mi * (16 * ROW_B) + ks * 32);
#pragma unroll
            for (int ni = 0; ni < 2; ni++)
                ldm_x4(bf_[ni], bufb + 1 * ARR_SZ + b_lbase
                                  + ni * (16 * ROW_B) + ks * 32);
#pragma unroll
            for (int mi = 0; mi < 4; mi++)
#pragma unroll
                for (int ni = 0; ni < 2; ni++) {
                    mma_fp16(acc[mi][ni * 2 + 0], ah[mi], bf_[ni][0], bf_[ni][2]);
                    mma_fp16(acc[mi][ni * 2 + 1], ah[mi], bf_[ni][1], bf_[ni][3]);
                }
        }
    }
#undef F_LD_STAGE

    const int erow = lane >> 2;
    const int ecol = (lane & 3) * 2;
#pragma unroll
    for (int mi = 0; mi < 4; mi++) {
#pragma unroll
        for (int nj = 0; nj < 4; nj++) {
            size_t base0 = (size_t)(m0 + m0w + mi * 16 + erow) * Dn
                         + n0 + n0w + nj * 8 + ecol;
            if (EPI == 0) {
                *(float2*)(C + base0)          = make_float2(acc[mi][nj][0], acc[mi][nj][1]);
                *(float2*)(C + base0 + 8 * Dn) = make_float2(acc[mi][nj][2], acc[mi][nj][3]);
            } else {
#pragma unroll
                for (int half = 0; half < 2; half++) {
                    size_t b = base0 + half * 8 * Dn;
                    uint32_t p = pack_f16x2(acc[mi][nj][half * 2 + 0],
                                            acc[mi][nj][half * 2 + 1]);
                    *(uint32_t*)(Cf + b) = p;
                }
            }
        }
    }
}

// Fused Q/K/V projection: grid (64, 24); y selects weight+n0 (Q first, V last
// in launch order so the short fp16 CTAs fill the final-wave tail).
__global__ __launch_bounds__(256, 2) void gemm_qkv(
    const __nv_bfloat16* __restrict__ Ahi, const __nv_bfloat16* __restrict__ Alo,
    const __half* __restrict__ Af,
    const __nv_bfloat16* __restrict__ Whi, const __nv_bfloat16* __restrict__ Wlo,
    const __half* __restrict__ Wf,
    __nv_bfloat16* __restrict__ Qh, __nv_bfloat16* __restrict__ Ql,
    __nv_bfloat16* __restrict__ Kh, __nv_bfloat16* __restrict__ Kl,
    __half* __restrict__ Vf, float qscale)
{
    const int un   = blockIdx.y;          // 0..23; slow axis -> launch order
    const int wsel = un >> 3;             // 0=Q (first), 1=K, 2=V (last)
    const int n0   = (un & 7) * 128;
    const int m0   = blockIdx.x * 128;
    if (wsel == 0)
        gemm_bf16_body(Ahi, Alo, Whi, Wlo, Qh, Ql, qscale, m0, n0);
    else if (wsel == 1)
        gemm_bf16_body(Ahi, Alo, Whi + (size_t)Dn * Dn, Wlo + (size_t)Dn * Dn,
                       Kh, Kl, 1.0f, m0, n0);
    else
        gemm_fp16_body<2>(Af, Wf, nullptr, Vf, m0, n0);
}

// O projection: fp16 single-term, fp32 output
__global__ __launch_bounds__(256, 2) void gemm_o(
    const __half* __restrict__ AVf, const __half* __restrict__ Wof,
    float* __restrict__ C)
{
    gemm_fp16_body<0>(AVf, Wof, C, nullptr,
                      blockIdx.y * 128, blockIdx.x * 128);
}

// ---------------------------------------------------------------------------
// Flash attention: QK^T = 3-term bf16 split; P*V = single fp16 MMA.
// Q staged via cp.async (overlaps KV issue), Q frags in registers,
// 3-stage KV ring, JIT exp/pack, rescale skip, fp16 AV out.
// ---------------------------------------------------------------------------
#define FROW 144
#define FARR (64 * FROW)          // 9216
#define QARR (128 * FROW)         // 18432
#define KVBUF (3 * FARR)          // 27648
#define FLASH_SMEM (QARR + 3 * KVBUF)   // 101376 -> 2 CTAs/SM

#define KV_PREFETCH(kt_, buf_) do {                                           \
    const uint32_t base_ = sb + QARR + (uint32_t)(buf_) * KVBUF;              \
    const size_t g0_ = (size_t)(bb * Sn + (kt_) * 64 + kr0) * Dn              \
                     + headoff + kch * 8;                                     \
    const size_t g1_ = g0_ + (size_t)32 * Dn;                                 \
    cp16(base_ + 0 * FARR + kso0, g_Kh + g0_);                                \
    cp16(base_ + 0 * FARR + kso1, g_Kh + g1_);                                \
    cp16(base_ + 1 * FARR + kso0, g_Kl + g0_);                                \
    cp16(base_ + 1 * FARR + kso1, g_Kl + g1_);                                \
    cp16(base_ + 2 * FARR + kso0, g_Vf + g0_);                                \
    cp16(base_ + 2 * FARR + kso1, g_Vf + g1_);                                \
    CP_COMMIT();                                                              \
} while (0)

__global__ __launch_bounds__(256, 2) void flash_mma()
{
    extern __shared__ char sm[];
    const uint32_t sb = smem_u32(sm);
    const int tid = threadIdx.x;
    const int lane = tid & 31;
    const int w = tid >> 5;
    const int qt = blockIdx.x, hh = blockIdx.y, bb = blockIdx.z;

    const size_t headoff = (size_t)hh * 64;

    const int kr0 = tid >> 3;
    const int kch = tid & 7;
    const uint32_t kso0 = (uint32_t)kr0 * FROW + kch * 16;
    const uint32_t kso1 = (uint32_t)(kr0 + 32) * FROW + kch * 16;

    // Prologue: Qh -> [0,QARR), Ql -> ring buffer 2 area, all via cp.async.
    const uint32_t qlbase = QARR + 2 * KVBUF;
#pragma unroll
    for (int i = 0; i < 4; i++) {
        const int idx = tid + 256 * i;
        const int r = idx >> 3, ch = idx & 7;
        const size_t g = (size_t)(bb * Sn + qt * 128 + r) * Dn + headoff + ch * 8;
        const uint32_t so = r * FROW + ch * 16;
        cp16(sb + so,          g_Qh + g);
        cp16(sb + qlbase + so, g_Ql + g);
    }
    CP_COMMIT();                 // group: Q
    KV_PREFETCH(0, 0);           // group: KV0
    KV_PREFETCH(1, 1);           // group: KV1
    CP_WAIT2();                  // Q resident (KV0/KV1 may still fly)
    __syncthreads();

    const int lrow = lane & 15;
    const int lch  = lane >> 4;
    const uint32_t aoff = (uint32_t)(w * 16 + lrow) * FROW + lch * 16;
    uint32_t boff[4];
#pragma unroll
    for (int np = 0; np < 4; np++)
        boff[np] = (uint32_t)(np * 16 + lrow) * FROW + lch * 16;

    uint32_t qhf[4][4], qlf[4][4];
#pragma unroll
    for (int ks = 0; ks < 4; ks++) {
        ldm_x4(qhf[ks], sb + aoff + ks * 32);
        ldm_x4(qlf[ks], sb + qlbase + aoff + ks * 32);
    }

    float o[8][4];
#pragma unroll
    for (int j = 0; j < 8; j++)
#pragma unroll
        for (int k = 0; k < 4; k++) o[j][k] = 0.f;
    float m0r = -1e30f, m1r = -1e30f, l0r = 0.f, l1r = 0.f;

    for (int kt = 0; kt < Sn / 64; kt++) {
        if (kt + 1 < Sn / 64) { CP_WAIT1(); } else { CP_WAIT0(); }
        __syncthreads();   // stage kt resident; prior reads (incl. q frags) done

        if (kt + 2 < Sn / 64)
            KV_PREFETCH(kt + 2, (kt + 2) % 3);

        const uint32_t kvb = sb + QARR + (uint32_t)(kt % 3) * KVBUF;

        float s[8][4];
#pragma unroll
        for (int j = 0; j < 8; j++)
#pragma unroll
            for (int k = 0; k < 4; k++) s[j][k] = 0.f;

#pragma unroll
        for (int ks = 0; ks < 4; ks++) {
#pragma unroll
            for (int np = 0; np < 4; np++) {
                uint32_t kh[4], kl[4];
                ldm_x4(kh, kvb + 0 * FARR + boff[np] + ks * 32);
                ldm_x4(kl, kvb + 1 * FARR + boff[np] + ks * 32);
                mma_bf16(s[2 * np + 0], qhf[ks], kh[0], kh[2]);
                mma_bf16(s[2 * np + 1], qhf[ks], kh[1], kh[3]);
                mma_bf16(s[2 * np + 0], qhf[ks], kl[0], kl[2]);
                mma_bf16(s[2 * np + 1], qhf[ks], kl[1], kl[3]);
                mma_bf16(s[2 * np + 0], qlf[ks], kh[0], kh[2]);
                mma_bf16(s[2 * np + 1], qlf[ks], kh[1], kh[3]);
            }
        }

        float mx0 = -1e30f, mx1 = -1e30f;
#pragma unroll
        for (int j = 0; j < 8; j++) {
            mx0 = fmaxf(mx0, fmaxf(s[j][0], s[j][1]));
            mx1 = fmaxf(mx1, fmaxf(s[j][2], s[j][3]));
        }
        mx0 = fmaxf(mx0, __shfl_xor_sync(0xffffffffu, mx0, 1));
        mx0 = fmaxf(mx0, __shfl_xor_sync(0xffffffffu, mx0, 2));
        mx1 = fmaxf(mx1, __shfl_xor_sync(0xffffffffu, mx1, 1));
        mx1 = fmaxf(mx1, __shfl_xor_sync(0xffffffffu, mx1, 2));

        const float mn0 = fmaxf(m0r, mx0);
        const float mn1 = fmaxf(m1r, mx1);
        float a0 = 1.0f, a1 = 1.0f;
        const bool upd = (mn0 > m0r) || (mn1 > m1r);
        if (__any_sync(0xffffffffu, upd)) {
            a0 = fast_ex2(m0r - mn0);
            a1 = fast_ex2(m1r - mn1);
#pragma unroll
            for (int j = 0; j < 8; j++) {
                o[j][0] *= a0; o[j][1] *= a0;
                o[j][2] *= a1; o[j][3] *= a1;
            }
        }
        m0r = mn0; m1r = mn1;

        float sum0 = 0.f, sum1 = 0.f;
#pragma unroll
        for (int ks = 0; ks < 4; ks++) {
            uint32_t ap[4];
#pragma unroll
            for (int jj = 0; jj < 2; jj++) {
                const int j = 2 * ks + jj;
                float p00 = fast_ex2(s[j][0] - mn0);
                float p01 = fast_ex2(s[j][1] - mn0);
                float p10 = fast_ex2(s[j][2] - mn1);
                float p11 = fast_ex2(s[j][3] - mn1);
                sum0 += p00 + p01;
                sum1 += p10 + p11;
                ap[jj * 2 + 0] = pack_f16x2(p00, p01);
                ap[jj * 2 + 1] = pack_f16x2(p10, p11);
            }
            const uint32_t vbase = (uint32_t)(ks * 16 + lrow) * FROW + lch * 16;
#pragma unroll
            for (int np = 0; np < 4; np++) {
                uint32_t vf[4];
                ldm_x4t(vf, kvb + 2 * FARR + vbase + np * 32);
                mma_fp16(o[2 * np + 0], ap, vf[0], vf[1]);
                mma_fp16(o[2 * np + 1], ap, vf[2], vf[3]);
            }
        }
        sum0 += __shfl_xor_sync(0xffffffffu, sum0, 1);
        sum0 += __shfl_xor_sync(0xffffffffu, sum0, 2);
        sum1 += __shfl_xor_sync(0xffffffffu, sum1, 1);
        sum1 += __shfl_xor_sync(0xffffffffu, sum1, 2);
        l0r = l0r * a0 + sum0;
        l1r = l1r * a1 + sum1;
    }

    // Epilogue: normalize, write AV as single fp16
    const float inv0 = 1.0f / l0r;
    const float inv1 = 1.0f / l1r;
    const size_t row0 = (size_t)(bb * Sn + qt * 128 + w * 16 + (lane >> 2));
    const size_t row1 = row0 + 8;
    const size_t colb = headoff + (lane & 3) * 2;
#pragma unroll
    for (int j = 0; j < 8; j++) {
        size_t b0 = row0 * Dn + colb + j * 8;
        size_t b1 = row1 * Dn + colb + j * 8;
        *(uint32_t*)(g_AVf + b0) = pack_f16x2(o[j][0] * inv0, o[j][1] * inv0);
        *(uint32_t*)(g_AVf + b1) = pack_f16x2(o[j][2] * inv1, o[j][3] * inv1);
    }
}

// ---------------------------------------------------------------------------
// Residual + LayerNorm
// ---------------------------------------------------------------------------
__global__ __launch_bounds__(256) void ln_residual(
    const float* __restrict__ h, const float* __restrict__ gamma,
    const float* __restrict__ beta, float* __restrict__ out)
{
    const int row = blockIdx.x;
    const int tid = threadIdx.x;

    const float4 hv = *(const float4*)(h + row * Dn + tid * 4);
    const float4 av = *(const float4*)(g_AO + row * Dn + tid * 4);
    float4 x = make_float4(hv.x + av.x, hv.y + av.y, hv.z + av.z, hv.w + av.w);

    float s  = x.x + x.y + x.z + x.w;
    float ss = x.x * x.x + x.y * x.y + x.z * x.z + x.w * x.w;
#pragma unroll
    for (int off = 16; off > 0; off >>= 1) {
        s  += __shfl_xor_sync(0xffffffffu, s, off);
        ss += __shfl_xor_sync(0xffffffffu, ss, off);
    }
    __shared__ float rs[8], rss[8];
    if ((tid & 31) == 0) { rs[tid >> 5] = s; rss[tid >> 5] = ss; }
    __syncthreads();
    s = 0.f; ss = 0.f;
#pragma unroll
    for (int w = 0; w < 8; w++) { s += rs[w]; ss += rss[w]; }

    const float mu  = s * (1.0f / Dn);
    const float var = ss * (1.0f / Dn) - mu * mu;
    const float inv = rsqrtf(var + 1e-5f);

    const float4 g4 = *(const float4*)(gamma + tid * 4);
    const float4 b4 = *(const float4*)(beta + tid * 4);
    float4 r;
    r.x = g4.x * (x.x - mu) * inv + b4.x;
    r.y = g4.y * (x.y - mu) * inv + b4.y;
    r.z = g4.z * (x.z - mu) * inv + b4.z;
    r.w = g4.w * (x.w - mu) * inv + b4.w;
    *(float4*)(out + row * Dn + tid * 4) = r;
}

// ---------------------------------------------------------------------------
extern "C" void kernel_launch(void* const* d_in, const int* in_sizes, int n_in,
                              void* d_out, int out_size)
{
    (void)in_sizes; (void)n_in; (void)out_size;
    const float* h     = (const float*)d_in[0];
    const float* Wq    = (const float*)d_in[1];
    const float* Wk    = (const float*)d_in[2];
    const float* Wv    = (const float*)d_in[3];
    const float* Wo    = (const float*)d_in[4];
    const float* gamma = (const float*)d_in[5];
    const float* beta  = (const float*)d_in[6];
    float* out = (float*)d_out;

    float* AOp;
    __nv_bfloat16 *hAhi, *hAlo, *Whi, *Wlo, *Qh, *Ql, *Kh, *Kl;
    __half *hF, *Wf, *Vf, *AVf;
    cudaGetSymbolAddress((void**)&AOp,  g_AO);
    cudaGetSymbolAddress((void**)&hAhi, g_hA_hi);
    cudaGetSymbolAddress((void**)&hAlo, g_hA_lo);
    cudaGetSymbolAddress((void**)&hF,   g_hF);
    cudaGetSymbolAddress((void**)&Whi,  g_W_hi);
    cudaGetSymbolAddress((void**)&Wlo,  g_W_lo);
    cudaGetSymbolAddress((void**)&Wf,   g_Wf);
    cudaGetSymbolAddress((void**)&Qh,   g_Qh);
    cudaGetSymbolAddress((void**)&Ql,   g_Ql);
    cudaGetSymbolAddress((void**)&Kh,   g_Kh);
    cudaGetSymbolAddress((void**)&Kl,   g_Kl);
    cudaGetSymbolAddress((void**)&Vf,   g_Vf);
    cudaGetSymbolAddress((void**)&AVf,  g_AVf);

    cudaFuncSetAttribute(gemm_qkv, cudaFuncAttributeMaxDynamicSharedMemorySize,
                         GEMM_SMEM);
    cudaFuncSetAttribute(gemm_o, cudaFuncAttributeMaxDynamicSharedMemorySize,
                         GEMM_SMEM);
    cudaFuncSetAttribute(flash_mma, cudaFuncAttributeMaxDynamicSharedMemorySize,
                         FLASH_SMEM);

    // Split h (bf16 pair + fp16 single) and weights
    split_h<<<Mn * Dn / 1024, 256>>>(h, hAhi, hAlo, hF);
    split_T4<<<dim3(32, 32, 4), dim3(32, 8)>>>(Wq, Wk, Wv, Wo, Whi, Wlo, Wf);

    // Fused Q/K/V projections: Q CTAs first, short V CTAs last (tail fill)
    const float QSCALE = 0.125f * 1.4426950408889634f;
    gemm_qkv<<<dim3(64, 24), 256, GEMM_SMEM>>>(
        hAhi, hAlo, hF, Whi, Wlo, Wf, Qh, Ql, Kh, Kl, Vf, QSCALE);

    // Attention (tensorized flash, fp16 PV, fp16 AV out)
    flash_mma<<<dim3(Sn / 128, Hn, Bn), 256, FLASH_SMEM>>>();

    // Output projection (single-term fp16)
    gemm_o<<<dim3(Dn / 128, Mn / 128), 256, GEMM_SMEM>>>(
        AVf, Wf + (size_t)Dn * Dn, AOp);

    ln_residual<<<Mn, 256>>>(h, gamma, beta, out);
}